// round 10
// baseline (speedup 1.0000x reference)
#include <cuda_runtime.h>
#include <math.h>
#include <stdint.h>

// Shapes (fixed by the problem)
#define BB 128
#define NN 512
#define TT 512
#define DD 256
#define KK 80

// -------- scratch (device globals; no allocation allowed) ----------
__device__ float g_CT[(size_t)BB * TT * DD];
__device__ float g_L [(size_t)BB * TT * NN];
__device__ float g_Sc[(size_t)BB * KK * NN];
__device__ float g_Cc[(size_t)BB * KK * TT];
__device__ float g_Hs[(size_t)BB * KK * NN];
__device__ float g_Hc[(size_t)BB * KK * TT];

// ---------------- helpers ----------------
__device__ __forceinline__ float ftf32(float x) {
    uint32_t u;
    asm("cvt.rna.tf32.f32 %0, %1;" : "=r"(u) : "f"(x));
    return __uint_as_float(u);
}

__device__ __forceinline__ void mma8(float& c0, float& c1, float& c2, float& c3,
                                     float a0, float a1, float a2, float a3,
                                     float b0, float b1) {
    asm volatile(
        "mma.sync.aligned.m16n8k8.row.col.f32.tf32.tf32.f32 "
        "{%0,%1,%2,%3},{%4,%5,%6,%7},{%8,%9},{%0,%1,%2,%3};"
        : "+f"(c0), "+f"(c1), "+f"(c2), "+f"(c3)
        : "r"(__float_as_uint(a0)), "r"(__float_as_uint(a1)),
          "r"(__float_as_uint(a2)), "r"(__float_as_uint(a3)),
          "r"(__float_as_uint(b0)), "r"(__float_as_uint(b1)));
}

// 3xTF32: acc += ahi*blo + alo*bhi + ahi*bhi   (lo*lo dropped, ~2^-22)
__device__ __forceinline__ void mma3(float* c,
                                     float2 aH0, float2 aH8, float2 aL0, float2 aL8,
                                     float2 bH, float2 bL) {
    mma8(c[0], c[1], c[2], c[3], aH0.x, aH8.x, aH0.y, aH8.y, bL.x, bL.y);
    mma8(c[0], c[1], c[2], c[3], aL0.x, aL8.x, aL0.y, aL8.y, bH.x, bH.y);
    mma8(c[0], c[1], c[2], c[3], aH0.x, aH8.x, aH0.y, aH8.y, bH.x, bH.y);
}

// smem tiles stored as float2 (k=p, k=p+4) at [buf][k8][p][row], hi & lo planes.
// stride 132/84 ≡ 4 (mod 16) in 8B banks -> conflict-free fragment fetches.

#define SMEM_A_F2 8448               // gemmA: 4 planes x 2112 float2
#define SMEM_A_BYTES (SMEM_A_F2 * 8) // 67584
#define SMEM_B_F2 6912               // gemmB: A planes 2x1344 + B planes 2x2112
#define SMEM_B_BYTES (SMEM_B_F2 * 8) // 55296

// ================= gemmA: BM=128, BN=128, BK=16, 256 thr =================
// C[M,N] = epi(A·op(B)); A [M,KD] row-major. BT: B [N,KD]; else B [KD,N].
template<int KD, bool BT, bool ADD, bool DOTANH>
__global__ __launch_bounds__(256) void gemmA(
    const float* __restrict__ A, const float* __restrict__ B,
    const float* __restrict__ Cadd, float* __restrict__ C,
    int N, long sA, long sB, long sC)
{
    extern __shared__ unsigned char smem_raw[];
    float2* AsH = (float2*)smem_raw;           // 2112
    float2* AsL = AsH + 2112;
    float2* BsH = AsH + 4224;
    float2* BsL = AsH + 6336;

    const int bz = blockIdx.z;
    A += (long)bz * sA;
    B += (long)bz * sB;
    C += (long)bz * sC;
    const float* Cad = ADD ? (Cadd + (long)bz * sC) : nullptr;

    const int m0 = blockIdx.y * 128, n0 = blockIdx.x * 128;
    const int tid = threadIdx.x, lane = tid & 31, w = tid >> 5;
    const int g = lane >> 2, t = lane & 3;
    const int wm = w & 1, wn = w >> 1;          // warp tile 64x32 at (wm*64, wn*32)

    const int lr  = tid >> 1;                    // loader row 0..127
    const int lk8 = tid & 1;

    auto idx = [](int buf, int k8, int p, int r) {
        return (((buf * 2 + k8) * 4 + p) * 132 + r);
    };

    float acc[4][4][4];
#pragma unroll
    for (int i = 0; i < 4; i++)
#pragma unroll
        for (int j = 0; j < 4; j++)
#pragma unroll
            for (int c = 0; c < 4; c++) acc[i][j][c] = 0.f;

    float4 va0, va1, vb0, vb1, vn0, vn1;

    auto loadA = [&](int k0) {
        const float* p = &A[(long)(m0 + lr) * KD + k0 + lk8 * 8];
        va0 = *(const float4*)p;
        va1 = *(const float4*)(p + 4);
    };
    auto storeA = [&](int buf) {
        float xs[4] = {va0.x, va0.y, va0.z, va0.w};
        float ys[4] = {va1.x, va1.y, va1.z, va1.w};
#pragma unroll
        for (int p = 0; p < 4; p++) {
            float hx = ftf32(xs[p]), hy = ftf32(ys[p]);
            AsH[idx(buf, lk8, p, lr)] = make_float2(hx, hy);
            AsL[idx(buf, lk8, p, lr)] = make_float2(ftf32(xs[p] - hx), ftf32(ys[p] - hy));
        }
    };
    auto loadB = [&](int k0) {
        if constexpr (BT) {
            const float* p = &B[(long)(n0 + lr) * KD + k0 + lk8 * 8];
            vb0 = *(const float4*)p;
            vb1 = *(const float4*)(p + 4);
        } else {
            int s0 = tid, s1 = tid + 256;       // 512 float4 slots: 16 k-rows x 32 nq
            int k_a = s0 >> 5, nq_a = (s0 & 31) * 4;
            int k_b = s1 >> 5, nq_b = (s1 & 31) * 4;
            vn0 = *(const float4*)&B[(long)(k0 + k_a) * N + n0 + nq_a];
            vn1 = *(const float4*)&B[(long)(k0 + k_b) * N + n0 + nq_b];
        }
    };
    auto storeB = [&](int buf) {
        if constexpr (BT) {
            float xs[4] = {vb0.x, vb0.y, vb0.z, vb0.w};
            float ys[4] = {vb1.x, vb1.y, vb1.z, vb1.w};
#pragma unroll
            for (int p = 0; p < 4; p++) {
                float hx = ftf32(xs[p]), hy = ftf32(ys[p]);
                BsH[idx(buf, lk8, p, lr)] = make_float2(hx, hy);
                BsL[idx(buf, lk8, p, lr)] = make_float2(ftf32(xs[p] - hx), ftf32(ys[p] - hy));
            }
        } else {
#pragma unroll
            for (int h = 0; h < 2; h++) {
                int s = tid + h * 256;
                int k = s >> 5, nq = (s & 31) * 4;
                int k8 = k >> 3, p = k & 3, hi = (k >> 2) & 1;
                float4 v = h ? vn1 : vn0;
                float vv[4] = {v.x, v.y, v.z, v.w};
                float* baseH = &BsH[idx(buf, k8, p, nq)].x;
                float* baseL = &BsL[idx(buf, k8, p, nq)].x;
#pragma unroll
                for (int c = 0; c < 4; c++) {
                    float hh = ftf32(vv[c]);
                    baseH[c * 2 + hi] = hh;
                    baseL[c * 2 + hi] = ftf32(vv[c] - hh);
                }
            }
        }
    };

    auto compute = [&](int buf) {
#pragma unroll
        for (int k8 = 0; k8 < 2; k8++) {
            float2 aH0[4], aH8[4], aL0[4], aL8[4], bH[4], bL[4];
#pragma unroll
            for (int i = 0; i < 4; i++) {
                int m = wm * 64 + i * 16 + g;
                aH0[i] = AsH[idx(buf, k8, t, m)];
                aH8[i] = AsH[idx(buf, k8, t, m + 8)];
                aL0[i] = AsL[idx(buf, k8, t, m)];
                aL8[i] = AsL[idx(buf, k8, t, m + 8)];
            }
#pragma unroll
            for (int j = 0; j < 4; j++) {
                int n = wn * 32 + j * 8 + g;
                bH[j] = BsH[idx(buf, k8, t, n)];
                bL[j] = BsL[idx(buf, k8, t, n)];
            }
#pragma unroll
            for (int i = 0; i < 4; i++)
#pragma unroll
                for (int j = 0; j < 4; j++)
                    mma3(acc[i][j], aH0[i], aH8[i], aL0[i], aL8[i], bH[j], bL[j]);
        }
    };

    // software pipeline, unrolled x2 so buffer indices are literals
    constexpr int NT = KD >> 4;                 // 16 or 32 (even)
    loadA(0); loadB(0);
    storeA(0); storeB(0);
    __syncthreads();
#pragma unroll 1
    for (int kt = 0; kt < NT - 2; kt += 2) {
        loadA((kt + 1) << 4); loadB((kt + 1) << 4);
        compute(0);
        storeA(1); storeB(1);
        __syncthreads();
        loadA((kt + 2) << 4); loadB((kt + 2) << 4);
        compute(1);
        storeA(0); storeB(0);
        __syncthreads();
    }
    loadA((NT - 1) << 4); loadB((NT - 1) << 4);
    compute(0);
    storeA(1); storeB(1);
    __syncthreads();
    compute(1);

#pragma unroll
    for (int i = 0; i < 4; i++) {
        int row = m0 + wm * 64 + i * 16 + g;
#pragma unroll
        for (int j = 0; j < 4; j++) {
            int col = n0 + wn * 32 + j * 8 + 2 * t;
            float v0 = acc[i][j][0], v1 = acc[i][j][1];
            float v2 = acc[i][j][2], v3 = acc[i][j][3];
            if (ADD) {
                v0 += Cad[(long)row * N + col];
                v1 += Cad[(long)row * N + col + 1];
                v2 += Cad[(long)(row + 8) * N + col];
                v3 += Cad[(long)(row + 8) * N + col + 1];
            }
            if (DOTANH) { v0 = tanhf(v0); v1 = tanhf(v1); v2 = tanhf(v2); v3 = tanhf(v3); }
            *(float2*)&C[(long)row * N + col]       = make_float2(v0, v1);
            *(float2*)&C[(long)(row + 8) * N + col] = make_float2(v2, v3);
        }
    }
}

// ================= gemmB: BM=80, BN=128, BK=16, 320 thr =================
// warp grid 5(m) x 2(n); warp tile 16x64. M fixed = 80.
template<int KD, bool BT, bool ADD, bool DOTANH>
__global__ __launch_bounds__(320) void gemmB(
    const float* __restrict__ A, const float* __restrict__ B,
    const float* __restrict__ Cadd, float* __restrict__ C,
    int N, long sA, long sB, long sC)
{
    extern __shared__ unsigned char smem_raw[];
    float2* AsH = (float2*)smem_raw;            // 1344
    float2* AsL = AsH + 1344;
    float2* BsH = AsH + 2688;                   // 2112
    float2* BsL = AsH + 4800;

    const int bz = blockIdx.z;
    A += (long)bz * sA;
    B += (long)bz * sB;
    C += (long)bz * sC;
    const float* Cad = ADD ? (Cadd + (long)bz * sC) : nullptr;

    const int n0 = blockIdx.x * 128;
    const int tid = threadIdx.x, lane = tid & 31, w = tid >> 5;
    const int g = lane >> 2, t = lane & 3;
    const int wm = w >> 1, wn = w & 1;

    auto aidx = [](int buf, int k8, int p, int r) {
        return (((buf * 2 + k8) * 4 + p) * 84 + r);
    };
    auto bidx = [](int buf, int k8, int p, int r) {
        return (((buf * 2 + k8) * 4 + p) * 132 + r);
    };

    float acc[8][4];
#pragma unroll
    for (int j = 0; j < 8; j++)
#pragma unroll
        for (int c = 0; c < 4; c++) acc[j][c] = 0.f;

    float4 va0, va1, vb0, vb1, vn0, vn1;
    const int lra = tid >> 1, lk8a = tid & 1;   // A loader (tid<160)
    const int lrb = tid >> 1, lk8b = tid & 1;   // B nt loader (tid<256)

    auto loadA = [&](int k0) {
        if (tid < 160) {
            const float* p = &A[(long)lra * KD + k0 + lk8a * 8];
            va0 = *(const float4*)p;
            va1 = *(const float4*)(p + 4);
        }
    };
    auto storeA = [&](int buf) {
        if (tid < 160) {
            float xs[4] = {va0.x, va0.y, va0.z, va0.w};
            float ys[4] = {va1.x, va1.y, va1.z, va1.w};
#pragma unroll
            for (int p = 0; p < 4; p++) {
                float hx = ftf32(xs[p]), hy = ftf32(ys[p]);
                AsH[aidx(buf, lk8a, p, lra)] = make_float2(hx, hy);
                AsL[aidx(buf, lk8a, p, lra)] = make_float2(ftf32(xs[p] - hx), ftf32(ys[p] - hy));
            }
        }
    };
    auto loadB = [&](int k0) {
        if constexpr (BT) {
            if (tid < 256) {
                const float* p = &B[(long)(n0 + lrb) * KD + k0 + lk8b * 8];
                vb0 = *(const float4*)p;
                vb1 = *(const float4*)(p + 4);
            }
        } else {
            int s0 = tid, s1 = tid + 320;       // 512 slots
            int k_a = s0 >> 5, nq_a = (s0 & 31) * 4;
            vn0 = *(const float4*)&B[(long)(k0 + k_a) * N + n0 + nq_a];
            if (s1 < 512) {
                int k_b = s1 >> 5, nq_b = (s1 & 31) * 4;
                vn1 = *(const float4*)&B[(long)(k0 + k_b) * N + n0 + nq_b];
            }
        }
    };
    auto storeB = [&](int buf) {
        if constexpr (BT) {
            if (tid < 256) {
                float xs[4] = {vb0.x, vb0.y, vb0.z, vb0.w};
                float ys[4] = {vb1.x, vb1.y, vb1.z, vb1.w};
#pragma unroll
                for (int p = 0; p < 4; p++) {
                    float hx = ftf32(xs[p]), hy = ftf32(ys[p]);
                    BsH[bidx(buf, lk8b, p, lrb)] = make_float2(hx, hy);
                    BsL[bidx(buf, lk8b, p, lrb)] = make_float2(ftf32(xs[p] - hx), ftf32(ys[p] - hy));
                }
            }
        } else {
#pragma unroll
            for (int h = 0; h < 2; h++) {
                int s = tid + h * 320;
                if (s < 512) {
                    int k = s >> 5, nq = (s & 31) * 4;
                    int k8 = k >> 3, p = k & 3, hi = (k >> 2) & 1;
                    float4 v = h ? vn1 : vn0;
                    float vv[4] = {v.x, v.y, v.z, v.w};
                    float* baseH = &BsH[bidx(buf, k8, p, nq)].x;
                    float* baseL = &BsL[bidx(buf, k8, p, nq)].x;
#pragma unroll
                    for (int c = 0; c < 4; c++) {
                        float hh = ftf32(vv[c]);
                        baseH[c * 2 + hi] = hh;
                        baseL[c * 2 + hi] = ftf32(vv[c] - hh);
                    }
                }
            }
        }
    };

    auto compute = [&](int buf) {
#pragma unroll
        for (int k8 = 0; k8 < 2; k8++) {
            int m = wm * 16 + g;
            float2 aH0 = AsH[aidx(buf, k8, t, m)];
            float2 aH8 = AsH[aidx(buf, k8, t, m + 8)];
            float2 aL0 = AsL[aidx(buf, k8, t, m)];
            float2 aL8 = AsL[aidx(buf, k8, t, m + 8)];
#pragma unroll
            for (int j = 0; j < 8; j++) {
                int n = wn * 64 + j * 8 + g;
                float2 bH = BsH[bidx(buf, k8, t, n)];
                float2 bL = BsL[bidx(buf, k8, t, n)];
                mma3(acc[j], aH0, aH8, aL0, aL8, bH, bL);
            }
        }
    };

    constexpr int NT = KD >> 4;                 // 16 or 32 (even)
    loadA(0); loadB(0);
    storeA(0); storeB(0);
    __syncthreads();
#pragma unroll 1
    for (int kt = 0; kt < NT - 2; kt += 2) {
        loadA((kt + 1) << 4); loadB((kt + 1) << 4);
        compute(0);
        storeA(1); storeB(1);
        __syncthreads();
        loadA((kt + 2) << 4); loadB((kt + 2) << 4);
        compute(1);
        storeA(0); storeB(0);
        __syncthreads();
    }
    loadA((NT - 1) << 4); loadB((NT - 1) << 4);
    compute(0);
    storeA(1); storeB(1);
    __syncthreads();
    compute(1);

    {
        int row = wm * 16 + g;                   // < 80 always
#pragma unroll
        for (int j = 0; j < 8; j++) {
            int col = n0 + wn * 64 + j * 8 + 2 * t;
            float v0 = acc[j][0], v1 = acc[j][1];
            float v2 = acc[j][2], v3 = acc[j][3];
            if (ADD) {
                v0 += Cad[(long)row * N + col];
                v1 += Cad[(long)row * N + col + 1];
                v2 += Cad[(long)(row + 8) * N + col];
                v3 += Cad[(long)(row + 8) * N + col + 1];
            }
            if (DOTANH) { v0 = tanhf(v0); v1 = tanhf(v1); v2 = tanhf(v2); v3 = tanhf(v3); }
            *(float2*)&C[(long)row * N + col]       = make_float2(v0, v1);
            *(float2*)&C[(long)(row + 8) * N + col] = make_float2(v2, v3);
        }
    }
}

// --------------- attention: logits -> softmax -> pooling ---------------
// grid (BB, 2): y==0 -> (Hs, whs, content, off 0); y==1 -> (Hc, whc, comments, off DD)
__global__ __launch_bounds__(256) void attn_k(
    const float* __restrict__ Hs, const float* __restrict__ whs,
    const float* __restrict__ Xs,
    const float* __restrict__ Hc, const float* __restrict__ whc,
    const float* __restrict__ Xc,
    float* __restrict__ out)
{
    const int b = blockIdx.x;
    const int side = blockIdx.y;
    const float* H  = side ? Hc  : Hs;
    const float* wh = side ? whc : whs;
    const float* X  = side ? Xc  : Xs;
    const int outOff = side ? DD : 0;

    const int tid = threadIdx.x;
    __shared__ float wgt[512];
    __shared__ float red[256];
    __shared__ float whsm[KK];

    if (tid < KK) whsm[tid] = wh[tid];
    __syncthreads();

    for (int n = tid; n < 512; n += 256) {
        const float* hp = H + (long)b * KK * 512 + n;
        float acc = 0.f;
#pragma unroll 8
        for (int k = 0; k < KK; k++) acc = fmaf(whsm[k], hp[(long)k * 512], acc);
        wgt[n] = acc;
    }
    __syncthreads();

    float m = fmaxf(wgt[tid], wgt[tid + 256]);
    red[tid] = m;
    __syncthreads();
    for (int s = 128; s > 0; s >>= 1) {
        if (tid < s) red[tid] = fmaxf(red[tid], red[tid + s]);
        __syncthreads();
    }
    const float mx = red[0];
    __syncthreads();

    float e0 = expf(wgt[tid] - mx);
    float e1 = expf(wgt[tid + 256] - mx);
    wgt[tid] = e0;
    wgt[tid + 256] = e1;
    red[tid] = e0 + e1;
    __syncthreads();
    for (int s = 128; s > 0; s >>= 1) {
        if (tid < s) red[tid] += red[tid + s];
        __syncthreads();
    }
    const float inv = 1.f / red[0];
    __syncthreads();

    const float* xp = X + (long)b * 512 * DD + tid;
    float acc = 0.f;
    for (int n = 0; n < 512; n++) acc = fmaf(xp[(long)n * DD], wgt[n], acc);
    out[(long)b * 512 + outOff + tid] = acc * inv;
}

// ------------------------------- launch -------------------------------
extern "C" void kernel_launch(void* const* d_in, const int* in_sizes, int n_in,
                              void* d_out, int out_size)
{
    const float* content  = (const float*)d_in[0];
    const float* comments = (const float*)d_in[1];
    const float* Wl       = (const float*)d_in[2];
    const float* Wc       = (const float*)d_in[3];
    const float* Ws       = (const float*)d_in[4];
    const float* whs      = (const float*)d_in[5];
    const float* whc      = (const float*)d_in[6];
    float* out = (float*)d_out;

    float *CT, *L, *Sc, *Cc, *Hs, *Hc;
    cudaGetSymbolAddress((void**)&CT, g_CT);
    cudaGetSymbolAddress((void**)&L,  g_L);
    cudaGetSymbolAddress((void**)&Sc, g_Sc);
    cudaGetSymbolAddress((void**)&Cc, g_Cc);
    cudaGetSymbolAddress((void**)&Hs, g_Hs);
    cudaGetSymbolAddress((void**)&Hc, g_Hc);

    // dynamic smem opt-in (>48KB); idempotent, not a stream op
    cudaFuncSetAttribute(gemmA<DD, false, false, false>, cudaFuncAttributeMaxDynamicSharedMemorySize, SMEM_A_BYTES);
    cudaFuncSetAttribute(gemmA<DD, true,  false, true >, cudaFuncAttributeMaxDynamicSharedMemorySize, SMEM_A_BYTES);
    cudaFuncSetAttribute(gemmB<DD, true,  false, false>, cudaFuncAttributeMaxDynamicSharedMemorySize, SMEM_B_BYTES);
    cudaFuncSetAttribute(gemmB<TT, false, true,  true >, cudaFuncAttributeMaxDynamicSharedMemorySize, SMEM_B_BYTES);
    cudaFuncSetAttribute(gemmB<NN, true,  true,  true >, cudaFuncAttributeMaxDynamicSharedMemorySize, SMEM_B_BYTES);

    // CT[b] = comments[b] @ Wl           [512,256], K=256 (nn, Wl broadcast)
    gemmA<DD, false, false, false><<<dim3(2, 4, BB), 256, SMEM_A_BYTES>>>(
        comments, Wl, nullptr, CT, DD, (long)TT * DD, 0, (long)TT * DD);

    // Sc[b] = Ws @ content[b]^T          [80,512], K=256 (nt)
    gemmB<DD, true, false, false><<<dim3(4, 1, BB), 320, SMEM_B_BYTES>>>(
        Ws, content, nullptr, Sc, NN, 0, (long)NN * DD, (long)KK * NN);

    // Cc[b] = Wc @ comments[b]^T         [80,512], K=256 (nt)
    gemmB<DD, true, false, false><<<dim3(4, 1, BB), 320, SMEM_B_BYTES>>>(
        Wc, comments, nullptr, Cc, TT, 0, (long)TT * DD, (long)KK * TT);

    // L[b] = tanh(CT[b] @ content[b]^T)  [512,512], K=256 (nt)
    gemmA<DD, true, false, true><<<dim3(4, 4, BB), 256, SMEM_A_BYTES>>>(
        CT, content, nullptr, L, NN, (long)TT * DD, (long)NN * DD, (long)TT * NN);

    // Hs[b] = tanh(Sc + Cc @ L)          [80,512], K=512 (nn)
    gemmB<TT, false, true, true><<<dim3(4, 1, BB), 320, SMEM_B_BYTES>>>(
        Cc, L, Sc, Hs, NN, (long)KK * TT, (long)TT * NN, (long)KK * NN);

    // Hc[b] = tanh(Cc + Sc @ L^T)        [80,512], K=512 (nt)
    gemmB<NN, true, true, true><<<dim3(4, 1, BB), 320, SMEM_B_BYTES>>>(
        Sc, L, Cc, Hc, TT, (long)KK * NN, (long)TT * NN, (long)KK * TT);

    // fused attention + pooling (both sides in one launch)
    attn_k<<<dim3(BB, 2), 256>>>(Hs, whs, content, Hc, whc, comments, out);
}

// round 11
// speedup vs baseline: 1.0657x; 1.0657x over previous
#include <cuda_runtime.h>
#include <math.h>
#include <stdint.h>

// Shapes (fixed by the problem)
#define BB 128
#define NN 512
#define TT 512
#define DD 256
#define KK 80

// -------- scratch (device globals; no allocation allowed) ----------
__device__ float g_CT[(size_t)BB * TT * DD];
__device__ float g_L [(size_t)BB * TT * NN];
__device__ float g_Sc[(size_t)BB * KK * NN];
__device__ float g_Cc[(size_t)BB * KK * TT];
__device__ float g_Hs[(size_t)BB * KK * NN];
__device__ float g_Hc[(size_t)BB * KK * TT];

// ---------------- helpers ----------------
__device__ __forceinline__ float ftf32(float x) {
    uint32_t u;
    asm("cvt.rna.tf32.f32 %0, %1;" : "=r"(u) : "f"(x));
    return __uint_as_float(u);
}

__device__ __forceinline__ void mma8(float& c0, float& c1, float& c2, float& c3,
                                     float a0, float a1, float a2, float a3,
                                     float b0, float b1) {
    asm volatile(
        "mma.sync.aligned.m16n8k8.row.col.f32.tf32.tf32.f32 "
        "{%0,%1,%2,%3},{%4,%5,%6,%7},{%8,%9},{%0,%1,%2,%3};"
        : "+f"(c0), "+f"(c1), "+f"(c2), "+f"(c3)
        : "r"(__float_as_uint(a0)), "r"(__float_as_uint(a1)),
          "r"(__float_as_uint(a2)), "r"(__float_as_uint(a3)),
          "r"(__float_as_uint(b0)), "r"(__float_as_uint(b1)));
}

// 3xTF32: acc += ahi*blo + alo*bhi + ahi*bhi   (lo*lo dropped, ~2^-22)
__device__ __forceinline__ void mma3(float* c,
                                     float2 aH0, float2 aH8, float2 aL0, float2 aL8,
                                     float2 bH, float2 bL) {
    mma8(c[0], c[1], c[2], c[3], aH0.x, aH8.x, aH0.y, aH8.y, bL.x, bL.y);
    mma8(c[0], c[1], c[2], c[3], aL0.x, aL8.x, aL0.y, aL8.y, bH.x, bH.y);
    mma8(c[0], c[1], c[2], c[3], aH0.x, aH8.x, aH0.y, aH8.y, bH.x, bH.y);
}

// smem tiles stored as float2 (k=p, k=p+4) at [buf][k8][p][row], hi & lo planes.
// stride 132/84 ≡ 4 (mod 16) in 8B banks -> conflict-free fragment fetches.

#define SMEM_A_F2 8448               // gemmA: 4 planes x 2112 float2
#define SMEM_A_BYTES (SMEM_A_F2 * 8) // 67584
#define SMEM_B_F2 6912               // gemmB: A planes 2x1344 + B planes 2x2112
#define SMEM_B_BYTES (SMEM_B_F2 * 8) // 55296

// ================= gemmA: BM=128, BN=128, BK=16, 256 thr =================
// C[M,N] = epi(A·op(B)); A [M,KD] row-major. BT: B [N,KD]; else B [KD,N].
// __launch_bounds__(256,2): cap regs at 128 so 2 CTAs/SM fit the register file.
template<int KD, bool BT, bool ADD, bool DOTANH>
__global__ __launch_bounds__(256, 2) void gemmA(
    const float* __restrict__ A, const float* __restrict__ B,
    const float* __restrict__ Cadd, float* __restrict__ C,
    int N, long sA, long sB, long sC)
{
    extern __shared__ unsigned char smem_raw[];
    float2* AsH = (float2*)smem_raw;           // 2112
    float2* AsL = AsH + 2112;
    float2* BsH = AsH + 4224;
    float2* BsL = AsH + 6336;

    const int bz = blockIdx.z;
    A += (long)bz * sA;
    B += (long)bz * sB;
    C += (long)bz * sC;
    const float* Cad = ADD ? (Cadd + (long)bz * sC) : nullptr;

    const int m0 = blockIdx.y * 128, n0 = blockIdx.x * 128;
    const int tid = threadIdx.x, lane = tid & 31, w = tid >> 5;
    const int g = lane >> 2, t = lane & 3;
    const int wm = w & 1, wn = w >> 1;          // warp tile 64x32 at (wm*64, wn*32)

    const int lr  = tid >> 1;                    // loader row 0..127
    const int lk8 = tid & 1;

    auto idx = [](int buf, int k8, int p, int r) {
        return (((buf * 2 + k8) * 4 + p) * 132 + r);
    };

    float acc[4][4][4];
#pragma unroll
    for (int i = 0; i < 4; i++)
#pragma unroll
        for (int j = 0; j < 4; j++)
#pragma unroll
            for (int c = 0; c < 4; c++) acc[i][j][c] = 0.f;

    float4 va0, va1, vb0, vb1, vn0, vn1;

    auto loadA = [&](int k0) {
        const float* p = &A[(long)(m0 + lr) * KD + k0 + lk8 * 8];
        va0 = *(const float4*)p;
        va1 = *(const float4*)(p + 4);
    };
    auto storeA = [&](int buf) {
        float xs[4] = {va0.x, va0.y, va0.z, va0.w};
        float ys[4] = {va1.x, va1.y, va1.z, va1.w};
#pragma unroll
        for (int p = 0; p < 4; p++) {
            float hx = ftf32(xs[p]), hy = ftf32(ys[p]);
            AsH[idx(buf, lk8, p, lr)] = make_float2(hx, hy);
            AsL[idx(buf, lk8, p, lr)] = make_float2(ftf32(xs[p] - hx), ftf32(ys[p] - hy));
        }
    };
    auto loadB = [&](int k0) {
        if constexpr (BT) {
            const float* p = &B[(long)(n0 + lr) * KD + k0 + lk8 * 8];
            vb0 = *(const float4*)p;
            vb1 = *(const float4*)(p + 4);
        } else {
            int s0 = tid, s1 = tid + 256;       // 512 float4 slots: 16 k-rows x 32 nq
            int k_a = s0 >> 5, nq_a = (s0 & 31) * 4;
            int k_b = s1 >> 5, nq_b = (s1 & 31) * 4;
            vn0 = *(const float4*)&B[(long)(k0 + k_a) * N + n0 + nq_a];
            vn1 = *(const float4*)&B[(long)(k0 + k_b) * N + n0 + nq_b];
        }
    };
    auto storeB = [&](int buf) {
        if constexpr (BT) {
            float xs[4] = {vb0.x, vb0.y, vb0.z, vb0.w};
            float ys[4] = {vb1.x, vb1.y, vb1.z, vb1.w};
#pragma unroll
            for (int p = 0; p < 4; p++) {
                float hx = ftf32(xs[p]), hy = ftf32(ys[p]);
                BsH[idx(buf, lk8, p, lr)] = make_float2(hx, hy);
                BsL[idx(buf, lk8, p, lr)] = make_float2(ftf32(xs[p] - hx), ftf32(ys[p] - hy));
            }
        } else {
#pragma unroll
            for (int h = 0; h < 2; h++) {
                int s = tid + h * 256;
                int k = s >> 5, nq = (s & 31) * 4;
                int k8 = k >> 3, p = k & 3, hi = (k >> 2) & 1;
                float4 v = h ? vn1 : vn0;
                float vv[4] = {v.x, v.y, v.z, v.w};
                float* baseH = &BsH[idx(buf, k8, p, nq)].x;
                float* baseL = &BsL[idx(buf, k8, p, nq)].x;
#pragma unroll
                for (int c = 0; c < 4; c++) {
                    float hh = ftf32(vv[c]);
                    baseH[c * 2 + hi] = hh;
                    baseL[c * 2 + hi] = ftf32(vv[c] - hh);
                }
            }
        }
    };

    auto compute = [&](int buf) {
#pragma unroll
        for (int k8 = 0; k8 < 2; k8++) {
            float2 aH0[4], aH8[4], aL0[4], aL8[4];
#pragma unroll
            for (int i = 0; i < 4; i++) {
                int m = wm * 64 + i * 16 + g;
                aH0[i] = AsH[idx(buf, k8, t, m)];
                aH8[i] = AsH[idx(buf, k8, t, m + 8)];
                aL0[i] = AsL[idx(buf, k8, t, m)];
                aL8[i] = AsL[idx(buf, k8, t, m + 8)];
            }
            // stream B fragments (keeps live registers under the 128 cap)
#pragma unroll
            for (int j = 0; j < 4; j++) {
                int n = wn * 32 + j * 8 + g;
                float2 bH = BsH[idx(buf, k8, t, n)];
                float2 bL = BsL[idx(buf, k8, t, n)];
#pragma unroll
                for (int i = 0; i < 4; i++)
                    mma3(acc[i][j], aH0[i], aH8[i], aL0[i], aL8[i], bH, bL);
            }
        }
    };

    // software pipeline, unrolled x2 so buffer indices are literals
    constexpr int NT = KD >> 4;                 // 16 or 32 (even)
    loadA(0); loadB(0);
    storeA(0); storeB(0);
    __syncthreads();
#pragma unroll 1
    for (int kt = 0; kt < NT - 2; kt += 2) {
        loadA((kt + 1) << 4); loadB((kt + 1) << 4);
        compute(0);
        storeA(1); storeB(1);
        __syncthreads();
        loadA((kt + 2) << 4); loadB((kt + 2) << 4);
        compute(1);
        storeA(0); storeB(0);
        __syncthreads();
    }
    loadA((NT - 1) << 4); loadB((NT - 1) << 4);
    compute(0);
    storeA(1); storeB(1);
    __syncthreads();
    compute(1);

#pragma unroll
    for (int i = 0; i < 4; i++) {
        int row = m0 + wm * 64 + i * 16 + g;
#pragma unroll
        for (int j = 0; j < 4; j++) {
            int col = n0 + wn * 32 + j * 8 + 2 * t;
            float v0 = acc[i][j][0], v1 = acc[i][j][1];
            float v2 = acc[i][j][2], v3 = acc[i][j][3];
            if (ADD) {
                v0 += Cad[(long)row * N + col];
                v1 += Cad[(long)row * N + col + 1];
                v2 += Cad[(long)(row + 8) * N + col];
                v3 += Cad[(long)(row + 8) * N + col + 1];
            }
            if (DOTANH) { v0 = tanhf(v0); v1 = tanhf(v1); v2 = tanhf(v2); v3 = tanhf(v3); }
            *(float2*)&C[(long)row * N + col]       = make_float2(v0, v1);
            *(float2*)&C[(long)(row + 8) * N + col] = make_float2(v2, v3);
        }
    }
}

// ================= gemmB: BM=80, BN=128, BK=16, 320 thr =================
// warp grid 5(m) x 2(n); warp tile 16x64. M fixed = 80.
// __launch_bounds__(320,2): cap regs (<=102) so 2 CTAs/SM fit the register file.
template<int KD, bool BT, bool ADD, bool DOTANH>
__global__ __launch_bounds__(320, 2) void gemmB(
    const float* __restrict__ A, const float* __restrict__ B,
    const float* __restrict__ Cadd, float* __restrict__ C,
    int N, long sA, long sB, long sC)
{
    extern __shared__ unsigned char smem_raw[];
    float2* AsH = (float2*)smem_raw;            // 1344
    float2* AsL = AsH + 1344;
    float2* BsH = AsH + 2688;                   // 2112
    float2* BsL = AsH + 4800;

    const int bz = blockIdx.z;
    A += (long)bz * sA;
    B += (long)bz * sB;
    C += (long)bz * sC;
    const float* Cad = ADD ? (Cadd + (long)bz * sC) : nullptr;

    const int n0 = blockIdx.x * 128;
    const int tid = threadIdx.x, lane = tid & 31, w = tid >> 5;
    const int g = lane >> 2, t = lane & 3;
    const int wm = w >> 1, wn = w & 1;

    auto aidx = [](int buf, int k8, int p, int r) {
        return (((buf * 2 + k8) * 4 + p) * 84 + r);
    };
    auto bidx = [](int buf, int k8, int p, int r) {
        return (((buf * 2 + k8) * 4 + p) * 132 + r);
    };

    float acc[8][4];
#pragma unroll
    for (int j = 0; j < 8; j++)
#pragma unroll
        for (int c = 0; c < 4; c++) acc[j][c] = 0.f;

    float4 va0, va1, vb0, vb1, vn0, vn1;
    const int lra = tid >> 1, lk8a = tid & 1;   // A loader (tid<160)
    const int lrb = tid >> 1, lk8b = tid & 1;   // B nt loader (tid<256)

    auto loadA = [&](int k0) {
        if (tid < 160) {
            const float* p = &A[(long)lra * KD + k0 + lk8a * 8];
            va0 = *(const float4*)p;
            va1 = *(const float4*)(p + 4);
        }
    };
    auto storeA = [&](int buf) {
        if (tid < 160) {
            float xs[4] = {va0.x, va0.y, va0.z, va0.w};
            float ys[4] = {va1.x, va1.y, va1.z, va1.w};
#pragma unroll
            for (int p = 0; p < 4; p++) {
                float hx = ftf32(xs[p]), hy = ftf32(ys[p]);
                AsH[aidx(buf, lk8a, p, lra)] = make_float2(hx, hy);
                AsL[aidx(buf, lk8a, p, lra)] = make_float2(ftf32(xs[p] - hx), ftf32(ys[p] - hy));
            }
        }
    };
    auto loadB = [&](int k0) {
        if constexpr (BT) {
            if (tid < 256) {
                const float* p = &B[(long)(n0 + lrb) * KD + k0 + lk8b * 8];
                vb0 = *(const float4*)p;
                vb1 = *(const float4*)(p + 4);
            }
        } else {
            int s0 = tid, s1 = tid + 320;       // 512 slots
            int k_a = s0 >> 5, nq_a = (s0 & 31) * 4;
            vn0 = *(const float4*)&B[(long)(k0 + k_a) * N + n0 + nq_a];
            if (s1 < 512) {
                int k_b = s1 >> 5, nq_b = (s1 & 31) * 4;
                vn1 = *(const float4*)&B[(long)(k0 + k_b) * N + n0 + nq_b];
            }
        }
    };
    auto storeB = [&](int buf) {
        if constexpr (BT) {
            if (tid < 256) {
                float xs[4] = {vb0.x, vb0.y, vb0.z, vb0.w};
                float ys[4] = {vb1.x, vb1.y, vb1.z, vb1.w};
#pragma unroll
                for (int p = 0; p < 4; p++) {
                    float hx = ftf32(xs[p]), hy = ftf32(ys[p]);
                    BsH[bidx(buf, lk8b, p, lrb)] = make_float2(hx, hy);
                    BsL[bidx(buf, lk8b, p, lrb)] = make_float2(ftf32(xs[p] - hx), ftf32(ys[p] - hy));
                }
            }
        } else {
#pragma unroll
            for (int h = 0; h < 2; h++) {
                int s = tid + h * 320;
                if (s < 512) {
                    int k = s >> 5, nq = (s & 31) * 4;
                    int k8 = k >> 3, p = k & 3, hi = (k >> 2) & 1;
                    float4 v = h ? vn1 : vn0;
                    float vv[4] = {v.x, v.y, v.z, v.w};
                    float* baseH = &BsH[bidx(buf, k8, p, nq)].x;
                    float* baseL = &BsL[bidx(buf, k8, p, nq)].x;
#pragma unroll
                    for (int c = 0; c < 4; c++) {
                        float hh = ftf32(vv[c]);
                        baseH[c * 2 + hi] = hh;
                        baseL[c * 2 + hi] = ftf32(vv[c] - hh);
                    }
                }
            }
        }
    };

    auto compute = [&](int buf) {
#pragma unroll
        for (int k8 = 0; k8 < 2; k8++) {
            int m = wm * 16 + g;
            float2 aH0 = AsH[aidx(buf, k8, t, m)];
            float2 aH8 = AsH[aidx(buf, k8, t, m + 8)];
            float2 aL0 = AsL[aidx(buf, k8, t, m)];
            float2 aL8 = AsL[aidx(buf, k8, t, m + 8)];
#pragma unroll
            for (int j = 0; j < 8; j++) {
                int n = wn * 64 + j * 8 + g;
                float2 bH = BsH[bidx(buf, k8, t, n)];
                float2 bL = BsL[bidx(buf, k8, t, n)];
                mma3(acc[j], aH0, aH8, aL0, aL8, bH, bL);
            }
        }
    };

    constexpr int NT = KD >> 4;                 // 16 or 32 (even)
    loadA(0); loadB(0);
    storeA(0); storeB(0);
    __syncthreads();
#pragma unroll 1
    for (int kt = 0; kt < NT - 2; kt += 2) {
        loadA((kt + 1) << 4); loadB((kt + 1) << 4);
        compute(0);
        storeA(1); storeB(1);
        __syncthreads();
        loadA((kt + 2) << 4); loadB((kt + 2) << 4);
        compute(1);
        storeA(0); storeB(0);
        __syncthreads();
    }
    loadA((NT - 1) << 4); loadB((NT - 1) << 4);
    compute(0);
    storeA(1); storeB(1);
    __syncthreads();
    compute(1);

    {
        int row = wm * 16 + g;                   // < 80 always
#pragma unroll
        for (int j = 0; j < 8; j++) {
            int col = n0 + wn * 64 + j * 8 + 2 * t;
            float v0 = acc[j][0], v1 = acc[j][1];
            float v2 = acc[j][2], v3 = acc[j][3];
            if (ADD) {
                v0 += Cad[(long)row * N + col];
                v1 += Cad[(long)row * N + col + 1];
                v2 += Cad[(long)(row + 8) * N + col];
                v3 += Cad[(long)(row + 8) * N + col + 1];
            }
            if (DOTANH) { v0 = tanhf(v0); v1 = tanhf(v1); v2 = tanhf(v2); v3 = tanhf(v3); }
            *(float2*)&C[(long)row * N + col]       = make_float2(v0, v1);
            *(float2*)&C[(long)(row + 8) * N + col] = make_float2(v2, v3);
        }
    }
}

// --------------- attention: logits -> softmax -> pooling ---------------
// grid (BB, 2): y==0 -> (Hs, whs, content, off 0); y==1 -> (Hc, whc, comments, off DD)
__global__ __launch_bounds__(256) void attn_k(
    const float* __restrict__ Hs, const float* __restrict__ whs,
    const float* __restrict__ Xs,
    const float* __restrict__ Hc, const float* __restrict__ whc,
    const float* __restrict__ Xc,
    float* __restrict__ out)
{
    const int b = blockIdx.x;
    const int side = blockIdx.y;
    const float* H  = side ? Hc  : Hs;
    const float* wh = side ? whc : whs;
    const float* X  = side ? Xc  : Xs;
    const int outOff = side ? DD : 0;

    const int tid = threadIdx.x;
    __shared__ float wgt[512];
    __shared__ float red[256];
    __shared__ float whsm[KK];

    if (tid < KK) whsm[tid] = wh[tid];
    __syncthreads();

    for (int n = tid; n < 512; n += 256) {
        const float* hp = H + (long)b * KK * 512 + n;
        float acc = 0.f;
#pragma unroll 8
        for (int k = 0; k < KK; k++) acc = fmaf(whsm[k], hp[(long)k * 512], acc);
        wgt[n] = acc;
    }
    __syncthreads();

    float m = fmaxf(wgt[tid], wgt[tid + 256]);
    red[tid] = m;
    __syncthreads();
    for (int s = 128; s > 0; s >>= 1) {
        if (tid < s) red[tid] = fmaxf(red[tid], red[tid + s]);
        __syncthreads();
    }
    const float mx = red[0];
    __syncthreads();

    float e0 = expf(wgt[tid] - mx);
    float e1 = expf(wgt[tid + 256] - mx);
    wgt[tid] = e0;
    wgt[tid + 256] = e1;
    red[tid] = e0 + e1;
    __syncthreads();
    for (int s = 128; s > 0; s >>= 1) {
        if (tid < s) red[tid] += red[tid + s];
        __syncthreads();
    }
    const float inv = 1.f / red[0];
    __syncthreads();

    const float* xp = X + (long)b * 512 * DD + tid;
    float acc = 0.f;
    for (int n = 0; n < 512; n++) acc = fmaf(xp[(long)n * DD], wgt[n], acc);
    out[(long)b * 512 + outOff + tid] = acc * inv;
}

// ------------------------------- launch -------------------------------
extern "C" void kernel_launch(void* const* d_in, const int* in_sizes, int n_in,
                              void* d_out, int out_size)
{
    const float* content  = (const float*)d_in[0];
    const float* comments = (const float*)d_in[1];
    const float* Wl       = (const float*)d_in[2];
    const float* Wc       = (const float*)d_in[3];
    const float* Ws       = (const float*)d_in[4];
    const float* whs      = (const float*)d_in[5];
    const float* whc      = (const float*)d_in[6];
    float* out = (float*)d_out;

    float *CT, *L, *Sc, *Cc, *Hs, *Hc;
    cudaGetSymbolAddress((void**)&CT, g_CT);
    cudaGetSymbolAddress((void**)&L,  g_L);
    cudaGetSymbolAddress((void**)&Sc, g_Sc);
    cudaGetSymbolAddress((void**)&Cc, g_Cc);
    cudaGetSymbolAddress((void**)&Hs, g_Hs);
    cudaGetSymbolAddress((void**)&Hc, g_Hc);

    // dynamic smem opt-in (>48KB); idempotent, not a stream op
    cudaFuncSetAttribute(gemmA<DD, false, false, false>, cudaFuncAttributeMaxDynamicSharedMemorySize, SMEM_A_BYTES);
    cudaFuncSetAttribute(gemmA<DD, true,  false, true >, cudaFuncAttributeMaxDynamicSharedMemorySize, SMEM_A_BYTES);
    cudaFuncSetAttribute(gemmB<DD, true,  false, false>, cudaFuncAttributeMaxDynamicSharedMemorySize, SMEM_B_BYTES);
    cudaFuncSetAttribute(gemmB<TT, false, true,  true >, cudaFuncAttributeMaxDynamicSharedMemorySize, SMEM_B_BYTES);
    cudaFuncSetAttribute(gemmB<NN, true,  true,  true >, cudaFuncAttributeMaxDynamicSharedMemorySize, SMEM_B_BYTES);

    // CT[b] = comments[b] @ Wl           [512,256], K=256 (nn, Wl broadcast)
    gemmA<DD, false, false, false><<<dim3(2, 4, BB), 256, SMEM_A_BYTES>>>(
        comments, Wl, nullptr, CT, DD, (long)TT * DD, 0, (long)TT * DD);

    // Sc[b] = Ws @ content[b]^T          [80,512], K=256 (nt)
    gemmB<DD, true, false, false><<<dim3(4, 1, BB), 320, SMEM_B_BYTES>>>(
        Ws, content, nullptr, Sc, NN, 0, (long)NN * DD, (long)KK * NN);

    // Cc[b] = Wc @ comments[b]^T         [80,512], K=256 (nt)
    gemmB<DD, true, false, false><<<dim3(4, 1, BB), 320, SMEM_B_BYTES>>>(
        Wc, comments, nullptr, Cc, TT, 0, (long)TT * DD, (long)KK * TT);

    // L[b] = tanh(CT[b] @ content[b]^T)  [512,512], K=256 (nt)
    gemmA<DD, true, false, true><<<dim3(4, 4, BB), 256, SMEM_A_BYTES>>>(
        CT, content, nullptr, L, NN, (long)TT * DD, (long)NN * DD, (long)TT * NN);

    // Hs[b] = tanh(Sc + Cc @ L)          [80,512], K=512 (nn)
    gemmB<TT, false, true, true><<<dim3(4, 1, BB), 320, SMEM_B_BYTES>>>(
        Cc, L, Sc, Hs, NN, (long)KK * TT, (long)TT * NN, (long)KK * NN);

    // Hc[b] = tanh(Cc + Sc @ L^T)        [80,512], K=512 (nt)
    gemmB<NN, true, true, true><<<dim3(4, 1, BB), 320, SMEM_B_BYTES>>>(
        Sc, L, Cc, Hc, TT, (long)KK * NN, (long)TT * NN, (long)KK * TT);

    // fused attention + pooling (both sides in one launch)
    attn_k<<<dim3(BB, 2), 256>>>(Hs, whs, content, Hc, whc, comments, out);
}

// round 16
// speedup vs baseline: 1.1160x; 1.0472x over previous
#include <cuda_runtime.h>
#include <math.h>
#include <stdint.h>

// Shapes (fixed by the problem)
#define BB 128
#define NN 512
#define TT 512
#define DD 256
#define KK 80

// -------- scratch (device globals; no allocation allowed) ----------
__device__ float g_CT [(size_t)BB * TT * DD];
__device__ float g_L  [(size_t)BB * TT * NN];
__device__ float g_Sc [(size_t)BB * KK * NN];
__device__ float g_Cc [(size_t)BB * KK * TT];
__device__ float g_Hs [(size_t)BB * KK * NN];
__device__ float g_Hc [(size_t)BB * KK * TT];
__device__ float g_WlT[(size_t)DD * DD];

// ---------------- helpers ----------------
__device__ __forceinline__ float ftf32(float x) {
    uint32_t u;
    asm("cvt.rna.tf32.f32 %0, %1;" : "=r"(u) : "f"(x));
    return __uint_as_float(u);
}

__device__ __forceinline__ void mma8(float& c0, float& c1, float& c2, float& c3,
                                     float a0, float a1, float a2, float a3,
                                     float b0, float b1) {
    asm volatile(
        "mma.sync.aligned.m16n8k8.row.col.f32.tf32.tf32.f32 "
        "{%0,%1,%2,%3},{%4,%5,%6,%7},{%8,%9},{%0,%1,%2,%3};"
        : "+f"(c0), "+f"(c1), "+f"(c2), "+f"(c3)
        : "r"(__float_as_uint(a0)), "r"(__float_as_uint(a1)),
          "r"(__float_as_uint(a2)), "r"(__float_as_uint(a3)),
          "r"(__float_as_uint(b0)), "r"(__float_as_uint(b1)));
}

// 3xTF32: acc += ahi*blo + alo*bhi + ahi*bhi   (lo*lo dropped, ~2^-22)
__device__ __forceinline__ void mma3(float* c,
                                     float2 aH0, float2 aH8, float2 aL0, float2 aL8,
                                     float2 bH, float2 bL) {
    mma8(c[0], c[1], c[2], c[3], aH0.x, aH8.x, aH0.y, aH8.y, bL.x, bL.y);
    mma8(c[0], c[1], c[2], c[3], aL0.x, aL8.x, aL0.y, aL8.y, bH.x, bH.y);
    mma8(c[0], c[1], c[2], c[3], aH0.x, aH8.x, aH0.y, aH8.y, bH.x, bH.y);
}

#define SMEM_A_F2 8448
#define SMEM_A_BYTES (SMEM_A_F2 * 8) // 67584
#define SMEM_B_F2 6912
#define SMEM_B_BYTES (SMEM_B_F2 * 8) // 55296

// ---------------- Wl transpose (256x256) ----------------
__global__ __launch_bounds__(256) void transW(const float* __restrict__ in,
                                              float* __restrict__ outp) {
    __shared__ float t[32][33];
    const int bx = blockIdx.x * 32, by = blockIdx.y * 32;
    const int lx = threadIdx.x & 31, ly = threadIdx.x >> 5;  // 32x8
#pragma unroll
    for (int r = 0; r < 32; r += 8)
        t[ly + r][lx] = in[(long)(by + ly + r) * DD + bx + lx];
    __syncthreads();
#pragma unroll
    for (int r = 0; r < 32; r += 8)
        outp[(long)(bx + ly + r) * DD + by + lx] = t[lx][ly + r];
}

// ================= gemmA: BM=128, BN=128, BK=16, 256 thr =================
// C[M,N] = epi(A·op(B)); A [M,KD] row-major. BT: B [N,KD]; else B [KD,N].
template<int KD, bool BT, bool ADD, bool DOTANH>
__global__ __launch_bounds__(256, 2) void gemmA(
    const float* __restrict__ A, const float* __restrict__ B,
    const float* __restrict__ Cadd, float* __restrict__ C,
    int N, long sA, long sB, long sC)
{
    extern __shared__ unsigned char smem_raw[];
    float2* AsH = (float2*)smem_raw;
    float2* AsL = AsH + 2112;
    float2* BsH = AsH + 4224;
    float2* BsL = AsH + 6336;

    const int bz = blockIdx.z;
    A += (long)bz * sA;
    B += (long)bz * sB;
    C += (long)bz * sC;
    const float* Cad = ADD ? (Cadd + (long)bz * sC) : nullptr;

    const int m0 = blockIdx.y * 128, n0 = blockIdx.x * 128;
    const int tid = threadIdx.x, lane = tid & 31, w = tid >> 5;
    const int g = lane >> 2, t = lane & 3;
    const int wm = w & 1, wn = w >> 1;

    const int lr  = tid >> 1;
    const int lk8 = tid & 1;

    auto idx = [](int buf, int k8, int p, int r) {
        return (((buf * 2 + k8) * 4 + p) * 132 + r);
    };

    float acc[4][4][4];
#pragma unroll
    for (int i = 0; i < 4; i++)
#pragma unroll
        for (int j = 0; j < 4; j++)
#pragma unroll
            for (int c = 0; c < 4; c++) acc[i][j][c] = 0.f;

    float4 va0, va1, vb0, vb1, vn0, vn1;

    auto loadA = [&](int k0) {
        const float* p = &A[(long)(m0 + lr) * KD + k0 + lk8 * 8];
        va0 = *(const float4*)p;
        va1 = *(const float4*)(p + 4);
    };
    auto storeA = [&](int buf) {
        float xs[4] = {va0.x, va0.y, va0.z, va0.w};
        float ys[4] = {va1.x, va1.y, va1.z, va1.w};
#pragma unroll
        for (int p = 0; p < 4; p++) {
            float hx = ftf32(xs[p]), hy = ftf32(ys[p]);
            AsH[idx(buf, lk8, p, lr)] = make_float2(hx, hy);
            AsL[idx(buf, lk8, p, lr)] = make_float2(ftf32(xs[p] - hx), ftf32(ys[p] - hy));
        }
    };
    auto loadB = [&](int k0) {
        if constexpr (BT) {
            const float* p = &B[(long)(n0 + lr) * KD + k0 + lk8 * 8];
            vb0 = *(const float4*)p;
            vb1 = *(const float4*)(p + 4);
        } else {
            int s0 = tid, s1 = tid + 256;
            int k_a = s0 >> 5, nq_a = (s0 & 31) * 4;
            int k_b = s1 >> 5, nq_b = (s1 & 31) * 4;
            vn0 = *(const float4*)&B[(long)(k0 + k_a) * N + n0 + nq_a];
            vn1 = *(const float4*)&B[(long)(k0 + k_b) * N + n0 + nq_b];
        }
    };
    auto storeB = [&](int buf) {
        if constexpr (BT) {
            float xs[4] = {vb0.x, vb0.y, vb0.z, vb0.w};
            float ys[4] = {vb1.x, vb1.y, vb1.z, vb1.w};
#pragma unroll
            for (int p = 0; p < 4; p++) {
                float hx = ftf32(xs[p]), hy = ftf32(ys[p]);
                BsH[idx(buf, lk8, p, lr)] = make_float2(hx, hy);
                BsL[idx(buf, lk8, p, lr)] = make_float2(ftf32(xs[p] - hx), ftf32(ys[p] - hy));
            }
        } else {
#pragma unroll
            for (int h = 0; h < 2; h++) {
                int s = tid + h * 256;
                int k = s >> 5, nq = (s & 31) * 4;
                int k8 = k >> 3, p = k & 3, hi = (k >> 2) & 1;
                float4 v = h ? vn1 : vn0;
                float vv[4] = {v.x, v.y, v.z, v.w};
                float* baseH = &BsH[idx(buf, k8, p, nq)].x;
                float* baseL = &BsL[idx(buf, k8, p, nq)].x;
#pragma unroll
                for (int c = 0; c < 4; c++) {
                    float hh = ftf32(vv[c]);
                    baseH[c * 2 + hi] = hh;
                    baseL[c * 2 + hi] = ftf32(vv[c] - hh);
                }
            }
        }
    };

    auto compute = [&](int buf) {
#pragma unroll
        for (int k8 = 0; k8 < 2; k8++) {
            float2 aH0[4], aH8[4], aL0[4], aL8[4];
#pragma unroll
            for (int i = 0; i < 4; i++) {
                int m = wm * 64 + i * 16 + g;
                aH0[i] = AsH[idx(buf, k8, t, m)];
                aH8[i] = AsH[idx(buf, k8, t, m + 8)];
                aL0[i] = AsL[idx(buf, k8, t, m)];
                aL8[i] = AsL[idx(buf, k8, t, m + 8)];
            }
#pragma unroll
            for (int j = 0; j < 4; j++) {
                int n = wn * 32 + j * 8 + g;
                float2 bH = BsH[idx(buf, k8, t, n)];
                float2 bL = BsL[idx(buf, k8, t, n)];
#pragma unroll
                for (int i = 0; i < 4; i++)
                    mma3(acc[i][j], aH0[i], aH8[i], aL0[i], aL8[i], bH, bL);
            }
        }
    };

    constexpr int NT = KD >> 4;
    loadA(0); loadB(0);
    storeA(0); storeB(0);
    __syncthreads();
#pragma unroll 1
    for (int kt = 0; kt < NT - 2; kt += 2) {
        loadA((kt + 1) << 4); loadB((kt + 1) << 4);
        compute(0);
        storeA(1); storeB(1);
        __syncthreads();
        loadA((kt + 2) << 4); loadB((kt + 2) << 4);
        compute(1);
        storeA(0); storeB(0);
        __syncthreads();
    }
    loadA((NT - 1) << 4); loadB((NT - 1) << 4);
    compute(0);
    storeA(1); storeB(1);
    __syncthreads();
    compute(1);

#pragma unroll
    for (int i = 0; i < 4; i++) {
        int row = m0 + wm * 64 + i * 16 + g;
#pragma unroll
        for (int j = 0; j < 4; j++) {
            int col = n0 + wn * 32 + j * 8 + 2 * t;
            float v0 = acc[i][j][0], v1 = acc[i][j][1];
            float v2 = acc[i][j][2], v3 = acc[i][j][3];
            if (ADD) {
                v0 += Cad[(long)row * N + col];
                v1 += Cad[(long)row * N + col + 1];
                v2 += Cad[(long)(row + 8) * N + col];
                v3 += Cad[(long)(row + 8) * N + col + 1];
            }
            if (DOTANH) { v0 = tanhf(v0); v1 = tanhf(v1); v2 = tanhf(v2); v3 = tanhf(v3); }
            *(float2*)&C[(long)row * N + col]       = make_float2(v0, v1);
            *(float2*)&C[(long)(row + 8) * N + col] = make_float2(v2, v3);
        }
    }
}

// ================= gemmB: BM=80, BN=128, BK=16, 320 thr =================
// warp grid 5(m) x 2(n); warp tile 16x64. M fixed = 80.
template<int KD, bool BT, bool ADD, bool DOTANH>
__global__ __launch_bounds__(320, 2) void gemmB(
    const float* __restrict__ A, const float* __restrict__ B,
    const float* __restrict__ Cadd, float* __restrict__ C,
    int N, long sA, long sB, long sC)
{
    extern __shared__ unsigned char smem_raw[];
    float2* AsH = (float2*)smem_raw;
    float2* AsL = AsH + 1344;
    float2* BsH = AsH + 2688;
    float2* BsL = AsH + 4800;

    const int bz = blockIdx.z;
    A += (long)bz * sA;
    B += (long)bz * sB;
    C += (long)bz * sC;
    const float* Cad = ADD ? (Cadd + (long)bz * sC) : nullptr;

    const int n0 = blockIdx.x * 128;
    const int tid = threadIdx.x, lane = tid & 31, w = tid >> 5;
    const int g = lane >> 2, t = lane & 3;
    const int wm = w >> 1, wn = w & 1;

    auto aidx = [](int buf, int k8, int p, int r) {
        return (((buf * 2 + k8) * 4 + p) * 84 + r);
    };
    auto bidx = [](int buf, int k8, int p, int r) {
        return (((buf * 2 + k8) * 4 + p) * 132 + r);
    };

    float acc[8][4];
#pragma unroll
    for (int j = 0; j < 8; j++)
#pragma unroll
        for (int c = 0; c < 4; c++) acc[j][c] = 0.f;

    float4 va0, va1, vb0, vb1, vn0, vn1;
    const int lra = tid >> 1, lk8a = tid & 1;
    const int lrb = tid >> 1, lk8b = tid & 1;

    auto loadA = [&](int k0) {
        if (tid < 160) {
            const float* p = &A[(long)lra * KD + k0 + lk8a * 8];
            va0 = *(const float4*)p;
            va1 = *(const float4*)(p + 4);
        }
    };
    auto storeA = [&](int buf) {
        if (tid < 160) {
            float xs[4] = {va0.x, va0.y, va0.z, va0.w};
            float ys[4] = {va1.x, va1.y, va1.z, va1.w};
#pragma unroll
            for (int p = 0; p < 4; p++) {
                float hx = ftf32(xs[p]), hy = ftf32(ys[p]);
                AsH[aidx(buf, lk8a, p, lra)] = make_float2(hx, hy);
                AsL[aidx(buf, lk8a, p, lra)] = make_float2(ftf32(xs[p] - hx), ftf32(ys[p] - hy));
            }
        }
    };
    auto loadB = [&](int k0) {
        if constexpr (BT) {
            if (tid < 256) {
                const float* p = &B[(long)(n0 + lrb) * KD + k0 + lk8b * 8];
                vb0 = *(const float4*)p;
                vb1 = *(const float4*)(p + 4);
            }
        } else {
            int s0 = tid, s1 = tid + 320;
            int k_a = s0 >> 5, nq_a = (s0 & 31) * 4;
            vn0 = *(const float4*)&B[(long)(k0 + k_a) * N + n0 + nq_a];
            if (s1 < 512) {
                int k_b = s1 >> 5, nq_b = (s1 & 31) * 4;
                vn1 = *(const float4*)&B[(long)(k0 + k_b) * N + n0 + nq_b];
            }
        }
    };
    auto storeB = [&](int buf) {
        if constexpr (BT) {
            if (tid < 256) {
                float xs[4] = {vb0.x, vb0.y, vb0.z, vb0.w};
                float ys[4] = {vb1.x, vb1.y, vb1.z, vb1.w};
#pragma unroll
                for (int p = 0; p < 4; p++) {
                    float hx = ftf32(xs[p]), hy = ftf32(ys[p]);
                    BsH[bidx(buf, lk8b, p, lrb)] = make_float2(hx, hy);
                    BsL[bidx(buf, lk8b, p, lrb)] = make_float2(ftf32(xs[p] - hx), ftf32(ys[p] - hy));
                }
            }
        } else {
#pragma unroll
            for (int h = 0; h < 2; h++) {
                int s = tid + h * 320;
                if (s < 512) {
                    int k = s >> 5, nq = (s & 31) * 4;
                    int k8 = k >> 3, p = k & 3, hi = (k >> 2) & 1;
                    float4 v = h ? vn1 : vn0;
                    float vv[4] = {v.x, v.y, v.z, v.w};
                    float* baseH = &BsH[bidx(buf, k8, p, nq)].x;
                    float* baseL = &BsL[bidx(buf, k8, p, nq)].x;
#pragma unroll
                    for (int c = 0; c < 4; c++) {
                        float hh = ftf32(vv[c]);
                        baseH[c * 2 + hi] = hh;
                        baseL[c * 2 + hi] = ftf32(vv[c] - hh);
                    }
                }
            }
        }
    };

    auto compute = [&](int buf) {
#pragma unroll
        for (int k8 = 0; k8 < 2; k8++) {
            int m = wm * 16 + g;
            float2 aH0 = AsH[aidx(buf, k8, t, m)];
            float2 aH8 = AsH[aidx(buf, k8, t, m + 8)];
            float2 aL0 = AsL[aidx(buf, k8, t, m)];
            float2 aL8 = AsL[aidx(buf, k8, t, m + 8)];
#pragma unroll
            for (int j = 0; j < 8; j++) {
                int n = wn * 64 + j * 8 + g;
                float2 bH = BsH[bidx(buf, k8, t, n)];
                float2 bL = BsL[bidx(buf, k8, t, n)];
                mma3(acc[j], aH0, aH8, aL0, aL8, bH, bL);
            }
        }
    };

    constexpr int NT = KD >> 4;
    loadA(0); loadB(0);
    storeA(0); storeB(0);
    __syncthreads();
#pragma unroll 1
    for (int kt = 0; kt < NT - 2; kt += 2) {
        loadA((kt + 1) << 4); loadB((kt + 1) << 4);
        compute(0);
        storeA(1); storeB(1);
        __syncthreads();
        loadA((kt + 2) << 4); loadB((kt + 2) << 4);
        compute(1);
        storeA(0); storeB(0);
        __syncthreads();
    }
    loadA((NT - 1) << 4); loadB((NT - 1) << 4);
    compute(0);
    storeA(1); storeB(1);
    __syncthreads();
    compute(1);

    {
        int row = wm * 16 + g;
#pragma unroll
        for (int j = 0; j < 8; j++) {
            int col = n0 + wn * 64 + j * 8 + 2 * t;
            float v0 = acc[j][0], v1 = acc[j][1];
            float v2 = acc[j][2], v3 = acc[j][3];
            if (ADD) {
                v0 += Cad[(long)row * N + col];
                v1 += Cad[(long)row * N + col + 1];
                v2 += Cad[(long)(row + 8) * N + col];
                v3 += Cad[(long)(row + 8) * N + col + 1];
            }
            if (DOTANH) { v0 = tanhf(v0); v1 = tanhf(v1); v2 = tanhf(v2); v3 = tanhf(v3); }
            *(float2*)&C[(long)row * N + col]       = make_float2(v0, v1);
            *(float2*)&C[(long)(row + 8) * N + col] = make_float2(v2, v3);
        }
    }
}

// ============ gemmSC: merged Sc & Cc (nt, K=DD, N=512, no epi) ============
// grid z in [0,256): z<128 -> Sc = Ws @ content^T ; else Cc = Wc @ comments^T
__global__ __launch_bounds__(320, 2) void gemmSC(
    const float* __restrict__ Ws_, const float* __restrict__ content_,
    float* __restrict__ Sc_,
    const float* __restrict__ Wc_, const float* __restrict__ comments_,
    float* __restrict__ Cc_)
{
    extern __shared__ unsigned char smem_raw[];
    float2* AsH = (float2*)smem_raw;
    float2* AsL = AsH + 1344;
    float2* BsH = AsH + 2688;
    float2* BsL = AsH + 4800;

    const int z = blockIdx.z;
    const int bz = z & 127;
    const bool first = z < 128;
    const float* A = first ? Ws_ : Wc_;
    const float* B = (first ? content_ : comments_) + (long)bz * NN * DD;
    float*       C = (first ? Sc_ : Cc_) + (long)bz * KK * NN;

    const int n0 = blockIdx.x * 128;
    const int tid = threadIdx.x, lane = tid & 31, w = tid >> 5;
    const int g = lane >> 2, t = lane & 3;
    const int wm = w >> 1, wn = w & 1;

    auto aidx = [](int buf, int k8, int p, int r) {
        return (((buf * 2 + k8) * 4 + p) * 84 + r);
    };
    auto bidx = [](int buf, int k8, int p, int r) {
        return (((buf * 2 + k8) * 4 + p) * 132 + r);
    };

    float acc[8][4];
#pragma unroll
    for (int j = 0; j < 8; j++)
#pragma unroll
        for (int c = 0; c < 4; c++) acc[j][c] = 0.f;

    float4 va0, va1, vb0, vb1;
    const int lra = tid >> 1, lk8a = tid & 1;

    auto loadA = [&](int k0) {
        if (tid < 160) {
            const float* p = &A[(long)lra * DD + k0 + lk8a * 8];
            va0 = *(const float4*)p;
            va1 = *(const float4*)(p + 4);
        }
    };
    auto storeA = [&](int buf) {
        if (tid < 160) {
            float xs[4] = {va0.x, va0.y, va0.z, va0.w};
            float ys[4] = {va1.x, va1.y, va1.z, va1.w};
#pragma unroll
            for (int p = 0; p < 4; p++) {
                float hx = ftf32(xs[p]), hy = ftf32(ys[p]);
                AsH[aidx(buf, lk8a, p, lra)] = make_float2(hx, hy);
                AsL[aidx(buf, lk8a, p, lra)] = make_float2(ftf32(xs[p] - hx), ftf32(ys[p] - hy));
            }
        }
    };
    auto loadB = [&](int k0) {
        if (tid < 256) {
            const float* p = &B[(long)(n0 + lra) * DD + k0 + lk8a * 8];
            vb0 = *(const float4*)p;
            vb1 = *(const float4*)(p + 4);
        }
    };
    auto storeB = [&](int buf) {
        if (tid < 256) {
            float xs[4] = {vb0.x, vb0.y, vb0.z, vb0.w};
            float ys[4] = {vb1.x, vb1.y, vb1.z, vb1.w};
#pragma unroll
            for (int p = 0; p < 4; p++) {
                float hx = ftf32(xs[p]), hy = ftf32(ys[p]);
                BsH[bidx(buf, lk8a, p, lra)] = make_float2(hx, hy);
                BsL[bidx(buf, lk8a, p, lra)] = make_float2(ftf32(xs[p] - hx), ftf32(ys[p] - hy));
            }
        }
    };

    auto compute = [&](int buf) {
#pragma unroll
        for (int k8 = 0; k8 < 2; k8++) {
            int m = wm * 16 + g;
            float2 aH0 = AsH[aidx(buf, k8, t, m)];
            float2 aH8 = AsH[aidx(buf, k8, t, m + 8)];
            float2 aL0 = AsL[aidx(buf, k8, t, m)];
            float2 aL8 = AsL[aidx(buf, k8, t, m + 8)];
#pragma unroll
            for (int j = 0; j < 8; j++) {
                int n = wn * 64 + j * 8 + g;
                float2 bH = BsH[bidx(buf, k8, t, n)];
                float2 bL = BsL[bidx(buf, k8, t, n)];
                mma3(acc[j], aH0, aH8, aL0, aL8, bH, bL);
            }
        }
    };

    constexpr int NT = DD >> 4;   // 16
    loadA(0); loadB(0);
    storeA(0); storeB(0);
    __syncthreads();
#pragma unroll 1
    for (int kt = 0; kt < NT - 2; kt += 2) {
        loadA((kt + 1) << 4); loadB((kt + 1) << 4);
        compute(0);
        storeA(1); storeB(1);
        __syncthreads();
        loadA((kt + 2) << 4); loadB((kt + 2) << 4);
        compute(1);
        storeA(0); storeB(0);
        __syncthreads();
    }
    loadA((NT - 1) << 4); loadB((NT - 1) << 4);
    compute(0);
    storeA(1); storeB(1);
    __syncthreads();
    compute(1);

    {
        int row = wm * 16 + g;
#pragma unroll
        for (int j = 0; j < 8; j++) {
            int col = n0 + wn * 64 + j * 8 + 2 * t;
            *(float2*)&C[(long)row * NN + col]       = make_float2(acc[j][0], acc[j][1]);
            *(float2*)&C[(long)(row + 8) * NN + col] = make_float2(acc[j][2], acc[j][3]);
        }
    }
}

// --------------- attention: logits -> softmax -> pooling ---------------
__global__ __launch_bounds__(256) void attn_k(
    const float* __restrict__ Hs, const float* __restrict__ whs,
    const float* __restrict__ Xs,
    const float* __restrict__ Hc, const float* __restrict__ whc,
    const float* __restrict__ Xc,
    float* __restrict__ out)
{
    const int b = blockIdx.x;
    const int side = blockIdx.y;
    const float* H  = side ? Hc  : Hs;
    const float* wh = side ? whc : whs;
    const float* X  = side ? Xc  : Xs;
    const int outOff = side ? DD : 0;

    const int tid = threadIdx.x;
    __shared__ float wgt[512];
    __shared__ float red[256];
    __shared__ float whsm[KK];

    if (tid < KK) whsm[tid] = wh[tid];
    __syncthreads();

    for (int n = tid; n < 512; n += 256) {
        const float* hp = H + (long)b * KK * 512 + n;
        float acc = 0.f;
#pragma unroll 8
        for (int k = 0; k < KK; k++) acc = fmaf(whsm[k], hp[(long)k * 512], acc);
        wgt[n] = acc;
    }
    __syncthreads();

    float m = fmaxf(wgt[tid], wgt[tid + 256]);
    red[tid] = m;
    __syncthreads();
    for (int s = 128; s > 0; s >>= 1) {
        if (tid < s) red[tid] = fmaxf(red[tid], red[tid + s]);
        __syncthreads();
    }
    const float mx = red[0];
    __syncthreads();

    float e0 = expf(wgt[tid] - mx);
    float e1 = expf(wgt[tid + 256] - mx);
    wgt[tid] = e0;
    wgt[tid + 256] = e1;
    red[tid] = e0 + e1;
    __syncthreads();
    for (int s = 128; s > 0; s >>= 1) {
        if (tid < s) red[tid] += red[tid + s];
        __syncthreads();
    }
    const float inv = 1.f / red[0];
    __syncthreads();

    const float* xp = X + (long)b * 512 * DD + tid;
    float acc = 0.f;
    for (int n = 0; n < 512; n++) acc = fmaf(xp[(long)n * DD], wgt[n], acc);
    out[(long)b * 512 + outOff + tid] = acc * inv;
}

// ------------------------------- launch -------------------------------
extern "C" void kernel_launch(void* const* d_in, const int* in_sizes, int n_in,
                              void* d_out, int out_size)
{
    const float* content  = (const float*)d_in[0];
    const float* comments = (const float*)d_in[1];
    const float* Wl       = (const float*)d_in[2];
    const float* Wc       = (const float*)d_in[3];
    const float* Ws       = (const float*)d_in[4];
    const float* whs      = (const float*)d_in[5];
    const float* whc      = (const float*)d_in[6];
    float* out = (float*)d_out;

    float *CT, *L, *Sc, *Cc, *Hs, *Hc, *WlT;
    cudaGetSymbolAddress((void**)&CT,  g_CT);
    cudaGetSymbolAddress((void**)&L,   g_L);
    cudaGetSymbolAddress((void**)&Sc,  g_Sc);
    cudaGetSymbolAddress((void**)&Cc,  g_Cc);
    cudaGetSymbolAddress((void**)&Hs,  g_Hs);
    cudaGetSymbolAddress((void**)&Hc,  g_Hc);
    cudaGetSymbolAddress((void**)&WlT, g_WlT);

    cudaFuncSetAttribute(gemmA<DD, true,  false, false>, cudaFuncAttributeMaxDynamicSharedMemorySize, SMEM_A_BYTES);
    cudaFuncSetAttribute(gemmA<DD, true,  false, true >, cudaFuncAttributeMaxDynamicSharedMemorySize, SMEM_A_BYTES);
    cudaFuncSetAttribute(gemmSC, cudaFuncAttributeMaxDynamicSharedMemorySize, SMEM_B_BYTES);
    cudaFuncSetAttribute(gemmB<TT, false, true,  true >, cudaFuncAttributeMaxDynamicSharedMemorySize, SMEM_B_BYTES);
    cudaFuncSetAttribute(gemmB<NN, true,  true,  true >, cudaFuncAttributeMaxDynamicSharedMemorySize, SMEM_B_BYTES);

    // WlT = Wl^T (tiny)
    transW<<<dim3(8, 8), 256>>>(Wl, WlT);

    // CT[b] = comments[b] @ Wl = comments[b] @ WlT^T   [512,256], K=256 (nt!)
    gemmA<DD, true, false, false><<<dim3(2, 4, BB), 256, SMEM_A_BYTES>>>(
        comments, WlT, nullptr, CT, DD, (long)TT * DD, 0, (long)TT * DD);

    // Sc & Cc merged: [80,512], K=256 (nt)
    gemmSC<<<dim3(4, 1, 2 * BB), 320, SMEM_B_BYTES>>>(
        Ws, content, Sc, Wc, comments, Cc);

    // L[b] = tanh(CT[b] @ content[b]^T)  [512,512], K=256 (nt)
    gemmA<DD, true, false, true><<<dim3(4, 4, BB), 256, SMEM_A_BYTES>>>(
        CT, content, nullptr, L, NN, (long)TT * DD, (long)NN * DD, (long)TT * NN);

    // Hs[b] = tanh(Sc + Cc @ L)          [80,512], K=512 (nn)
    gemmB<TT, false, true, true><<<dim3(4, 1, BB), 320, SMEM_B_BYTES>>>(
        Cc, L, Sc, Hs, NN, (long)KK * TT, (long)TT * NN, (long)KK * NN);

    // Hc[b] = tanh(Cc + Sc @ L^T)        [80,512], K=512 (nt)
    gemmB<NN, true, true, true><<<dim3(4, 1, BB), 320, SMEM_B_BYTES>>>(
        Sc, L, Cc, Hc, TT, (long)KK * NN, (long)TT * NN, (long)KK * TT);

    attn_k<<<dim3(BB, 2), 256>>>(Hs, whs, content, Hc, whc, comments, out);
}

// round 17
// speedup vs baseline: 1.1784x; 1.0559x over previous
#include <cuda_runtime.h>
#include <math.h>
#include <stdint.h>

// Shapes (fixed by the problem)
#define BB 128
#define NN 512
#define TT 512
#define DD 256
#define KK 80

// -------- scratch (device globals; no allocation allowed) ----------
__device__ float g_CT [(size_t)BB * TT * DD];
__device__ float g_L  [(size_t)BB * TT * NN];
__device__ float g_Sc [(size_t)BB * KK * NN];
__device__ float g_Cc [(size_t)BB * KK * TT];
__device__ float g_Hs [(size_t)BB * KK * NN];
__device__ float g_Hc [(size_t)BB * KK * TT];
__device__ float g_WlT[(size_t)DD * DD];

// ---------------- helpers ----------------
__device__ __forceinline__ float ftf32(float x) {
    uint32_t u;
    asm("cvt.rna.tf32.f32 %0, %1;" : "=r"(u) : "f"(x));
    return __uint_as_float(u);
}

__device__ __forceinline__ void mma8(float& c0, float& c1, float& c2, float& c3,
                                     float a0, float a1, float a2, float a3,
                                     float b0, float b1) {
    asm volatile(
        "mma.sync.aligned.m16n8k8.row.col.f32.tf32.tf32.f32 "
        "{%0,%1,%2,%3},{%4,%5,%6,%7},{%8,%9},{%0,%1,%2,%3};"
        : "+f"(c0), "+f"(c1), "+f"(c2), "+f"(c3)
        : "r"(__float_as_uint(a0)), "r"(__float_as_uint(a1)),
          "r"(__float_as_uint(a2)), "r"(__float_as_uint(a3)),
          "r"(__float_as_uint(b0)), "r"(__float_as_uint(b1)));
}

// 3xTF32: acc += ahi*blo + alo*bhi + ahi*bhi   (lo*lo dropped, ~2^-22)
__device__ __forceinline__ void mma3(float* c,
                                     float2 aH0, float2 aH8, float2 aL0, float2 aL8,
                                     float2 bH, float2 bL) {
    mma8(c[0], c[1], c[2], c[3], aH0.x, aH8.x, aH0.y, aH8.y, bL.x, bL.y);
    mma8(c[0], c[1], c[2], c[3], aL0.x, aL8.x, aL0.y, aL8.y, bH.x, bH.y);
    mma8(c[0], c[1], c[2], c[3], aH0.x, aH8.x, aH0.y, aH8.y, bH.x, bH.y);
}

#define SMEM_A_F2 8448
#define SMEM_A_BYTES (SMEM_A_F2 * 8) // 67584
#define SMEM_B_F2 6912
#define SMEM_B_BYTES (SMEM_B_F2 * 8) // 55296

// ---------------- Wl transpose (256x256) ----------------
__global__ __launch_bounds__(256) void transW(const float* __restrict__ in,
                                              float* __restrict__ outp) {
    __shared__ float t[32][33];
    const int bx = blockIdx.x * 32, by = blockIdx.y * 32;
    const int lx = threadIdx.x & 31, ly = threadIdx.x >> 5;  // 32x8
#pragma unroll
    for (int r = 0; r < 32; r += 8)
        t[ly + r][lx] = in[(long)(by + ly + r) * DD + bx + lx];
    __syncthreads();
#pragma unroll
    for (int r = 0; r < 32; r += 8)
        outp[(long)(bx + ly + r) * DD + by + lx] = t[lx][ly + r];
}

// ================= gemmA: BM=128, BN=128, BK=16, 256 thr =================
// C[M,N] = epi(A·op(B)); A [M,KD] row-major. BT: B [N,KD]; else B [KD,N].
template<int KD, bool BT, bool ADD, bool DOTANH>
__global__ __launch_bounds__(256, 2) void gemmA(
    const float* __restrict__ A, const float* __restrict__ B,
    const float* __restrict__ Cadd, float* __restrict__ C,
    int N, long sA, long sB, long sC)
{
    extern __shared__ unsigned char smem_raw[];
    float2* AsH = (float2*)smem_raw;
    float2* AsL = AsH + 2112;
    float2* BsH = AsH + 4224;
    float2* BsL = AsH + 6336;

    const int bz = blockIdx.z;
    A += (long)bz * sA;
    B += (long)bz * sB;
    C += (long)bz * sC;
    const float* Cad = ADD ? (Cadd + (long)bz * sC) : nullptr;

    const int m0 = blockIdx.y * 128, n0 = blockIdx.x * 128;
    const int tid = threadIdx.x, lane = tid & 31, w = tid >> 5;
    const int g = lane >> 2, t = lane & 3;
    const int wm = w & 1, wn = w >> 1;

    const int lr  = tid >> 1;
    const int lk8 = tid & 1;

    auto idx = [](int buf, int k8, int p, int r) {
        return (((buf * 2 + k8) * 4 + p) * 132 + r);
    };

    float acc[4][4][4];
#pragma unroll
    for (int i = 0; i < 4; i++)
#pragma unroll
        for (int j = 0; j < 4; j++)
#pragma unroll
            for (int c = 0; c < 4; c++) acc[i][j][c] = 0.f;

    float4 va0, va1, vb0, vb1, vn0, vn1;

    auto loadA = [&](int k0) {
        const float* p = &A[(long)(m0 + lr) * KD + k0 + lk8 * 8];
        va0 = *(const float4*)p;
        va1 = *(const float4*)(p + 4);
    };
    auto storeA = [&](int buf) {
        float xs[4] = {va0.x, va0.y, va0.z, va0.w};
        float ys[4] = {va1.x, va1.y, va1.z, va1.w};
#pragma unroll
        for (int p = 0; p < 4; p++) {
            float hx = ftf32(xs[p]), hy = ftf32(ys[p]);
            AsH[idx(buf, lk8, p, lr)] = make_float2(hx, hy);
            AsL[idx(buf, lk8, p, lr)] = make_float2(ftf32(xs[p] - hx), ftf32(ys[p] - hy));
        }
    };
    auto loadB = [&](int k0) {
        if constexpr (BT) {
            const float* p = &B[(long)(n0 + lr) * KD + k0 + lk8 * 8];
            vb0 = *(const float4*)p;
            vb1 = *(const float4*)(p + 4);
        } else {
            int s0 = tid, s1 = tid + 256;
            int k_a = s0 >> 5, nq_a = (s0 & 31) * 4;
            int k_b = s1 >> 5, nq_b = (s1 & 31) * 4;
            vn0 = *(const float4*)&B[(long)(k0 + k_a) * N + n0 + nq_a];
            vn1 = *(const float4*)&B[(long)(k0 + k_b) * N + n0 + nq_b];
        }
    };
    auto storeB = [&](int buf) {
        if constexpr (BT) {
            float xs[4] = {vb0.x, vb0.y, vb0.z, vb0.w};
            float ys[4] = {vb1.x, vb1.y, vb1.z, vb1.w};
#pragma unroll
            for (int p = 0; p < 4; p++) {
                float hx = ftf32(xs[p]), hy = ftf32(ys[p]);
                BsH[idx(buf, lk8, p, lr)] = make_float2(hx, hy);
                BsL[idx(buf, lk8, p, lr)] = make_float2(ftf32(xs[p] - hx), ftf32(ys[p] - hy));
            }
        } else {
#pragma unroll
            for (int h = 0; h < 2; h++) {
                int s = tid + h * 256;
                int k = s >> 5, nq = (s & 31) * 4;
                int k8 = k >> 3, p = k & 3, hi = (k >> 2) & 1;
                float4 v = h ? vn1 : vn0;
                float vv[4] = {v.x, v.y, v.z, v.w};
                float* baseH = &BsH[idx(buf, k8, p, nq)].x;
                float* baseL = &BsL[idx(buf, k8, p, nq)].x;
#pragma unroll
                for (int c = 0; c < 4; c++) {
                    float hh = ftf32(vv[c]);
                    baseH[c * 2 + hi] = hh;
                    baseL[c * 2 + hi] = ftf32(vv[c] - hh);
                }
            }
        }
    };

    auto compute = [&](int buf) {
#pragma unroll
        for (int k8 = 0; k8 < 2; k8++) {
            float2 aH0[4], aH8[4], aL0[4], aL8[4];
#pragma unroll
            for (int i = 0; i < 4; i++) {
                int m = wm * 64 + i * 16 + g;
                aH0[i] = AsH[idx(buf, k8, t, m)];
                aH8[i] = AsH[idx(buf, k8, t, m + 8)];
                aL0[i] = AsL[idx(buf, k8, t, m)];
                aL8[i] = AsL[idx(buf, k8, t, m + 8)];
            }
#pragma unroll
            for (int j = 0; j < 4; j++) {
                int n = wn * 32 + j * 8 + g;
                float2 bH = BsH[idx(buf, k8, t, n)];
                float2 bL = BsL[idx(buf, k8, t, n)];
#pragma unroll
                for (int i = 0; i < 4; i++)
                    mma3(acc[i][j], aH0[i], aH8[i], aL0[i], aL8[i], bH, bL);
            }
        }
    };

    constexpr int NT = KD >> 4;
    loadA(0); loadB(0);
    storeA(0); storeB(0);
    __syncthreads();
#pragma unroll 1
    for (int kt = 0; kt < NT - 2; kt += 2) {
        loadA((kt + 1) << 4); loadB((kt + 1) << 4);
        compute(0);
        storeA(1); storeB(1);
        __syncthreads();
        loadA((kt + 2) << 4); loadB((kt + 2) << 4);
        compute(1);
        storeA(0); storeB(0);
        __syncthreads();
    }
    loadA((NT - 1) << 4); loadB((NT - 1) << 4);
    compute(0);
    storeA(1); storeB(1);
    __syncthreads();
    compute(1);

#pragma unroll
    for (int i = 0; i < 4; i++) {
        int row = m0 + wm * 64 + i * 16 + g;
#pragma unroll
        for (int j = 0; j < 4; j++) {
            int col = n0 + wn * 32 + j * 8 + 2 * t;
            float v0 = acc[i][j][0], v1 = acc[i][j][1];
            float v2 = acc[i][j][2], v3 = acc[i][j][3];
            if (ADD) {
                v0 += Cad[(long)row * N + col];
                v1 += Cad[(long)row * N + col + 1];
                v2 += Cad[(long)(row + 8) * N + col];
                v3 += Cad[(long)(row + 8) * N + col + 1];
            }
            if (DOTANH) { v0 = tanhf(v0); v1 = tanhf(v1); v2 = tanhf(v2); v3 = tanhf(v3); }
            *(float2*)&C[(long)row * N + col]       = make_float2(v0, v1);
            *(float2*)&C[(long)(row + 8) * N + col] = make_float2(v2, v3);
        }
    }
}

// ============ gemmSC: merged Sc & Cc (nt, K=DD, N=512, no epi) ============
// grid z in [0,256): z<128 -> Sc = Ws @ content^T ; else Cc = Wc @ comments^T
__global__ __launch_bounds__(320, 2) void gemmSC(
    const float* __restrict__ Ws_, const float* __restrict__ content_,
    float* __restrict__ Sc_,
    const float* __restrict__ Wc_, const float* __restrict__ comments_,
    float* __restrict__ Cc_)
{
    extern __shared__ unsigned char smem_raw[];
    float2* AsH = (float2*)smem_raw;
    float2* AsL = AsH + 1344;
    float2* BsH = AsH + 2688;
    float2* BsL = AsH + 4800;

    const int z = blockIdx.z;
    const int bz = z & 127;
    const bool first = z < 128;
    const float* A = first ? Ws_ : Wc_;
    const float* B = (first ? content_ : comments_) + (long)bz * NN * DD;
    float*       C = (first ? Sc_ : Cc_) + (long)bz * KK * NN;

    const int n0 = blockIdx.x * 128;
    const int tid = threadIdx.x, lane = tid & 31, w = tid >> 5;
    const int g = lane >> 2, t = lane & 3;
    const int wm = w >> 1, wn = w & 1;

    auto aidx = [](int buf, int k8, int p, int r) {
        return (((buf * 2 + k8) * 4 + p) * 84 + r);
    };
    auto bidx = [](int buf, int k8, int p, int r) {
        return (((buf * 2 + k8) * 4 + p) * 132 + r);
    };

    float acc[8][4];
#pragma unroll
    for (int j = 0; j < 8; j++)
#pragma unroll
        for (int c = 0; c < 4; c++) acc[j][c] = 0.f;

    float4 va0, va1, vb0, vb1;
    const int lra = tid >> 1, lk8a = tid & 1;

    auto loadA = [&](int k0) {
        if (tid < 160) {
            const float* p = &A[(long)lra * DD + k0 + lk8a * 8];
            va0 = *(const float4*)p;
            va1 = *(const float4*)(p + 4);
        }
    };
    auto storeA = [&](int buf) {
        if (tid < 160) {
            float xs[4] = {va0.x, va0.y, va0.z, va0.w};
            float ys[4] = {va1.x, va1.y, va1.z, va1.w};
#pragma unroll
            for (int p = 0; p < 4; p++) {
                float hx = ftf32(xs[p]), hy = ftf32(ys[p]);
                AsH[aidx(buf, lk8a, p, lra)] = make_float2(hx, hy);
                AsL[aidx(buf, lk8a, p, lra)] = make_float2(ftf32(xs[p] - hx), ftf32(ys[p] - hy));
            }
        }
    };
    auto loadB = [&](int k0) {
        if (tid < 256) {
            const float* p = &B[(long)(n0 + lra) * DD + k0 + lk8a * 8];
            vb0 = *(const float4*)p;
            vb1 = *(const float4*)(p + 4);
        }
    };
    auto storeB = [&](int buf) {
        if (tid < 256) {
            float xs[4] = {vb0.x, vb0.y, vb0.z, vb0.w};
            float ys[4] = {vb1.x, vb1.y, vb1.z, vb1.w};
#pragma unroll
            for (int p = 0; p < 4; p++) {
                float hx = ftf32(xs[p]), hy = ftf32(ys[p]);
                BsH[bidx(buf, lk8a, p, lra)] = make_float2(hx, hy);
                BsL[bidx(buf, lk8a, p, lra)] = make_float2(ftf32(xs[p] - hx), ftf32(ys[p] - hy));
            }
        }
    };

    auto compute = [&](int buf) {
#pragma unroll
        for (int k8 = 0; k8 < 2; k8++) {
            int m = wm * 16 + g;
            float2 aH0 = AsH[aidx(buf, k8, t, m)];
            float2 aH8 = AsH[aidx(buf, k8, t, m + 8)];
            float2 aL0 = AsL[aidx(buf, k8, t, m)];
            float2 aL8 = AsL[aidx(buf, k8, t, m + 8)];
#pragma unroll
            for (int j = 0; j < 8; j++) {
                int n = wn * 64 + j * 8 + g;
                float2 bH = BsH[bidx(buf, k8, t, n)];
                float2 bL = BsL[bidx(buf, k8, t, n)];
                mma3(acc[j], aH0, aH8, aL0, aL8, bH, bL);
            }
        }
    };

    constexpr int NT = DD >> 4;   // 16
    loadA(0); loadB(0);
    storeA(0); storeB(0);
    __syncthreads();
#pragma unroll 1
    for (int kt = 0; kt < NT - 2; kt += 2) {
        loadA((kt + 1) << 4); loadB((kt + 1) << 4);
        compute(0);
        storeA(1); storeB(1);
        __syncthreads();
        loadA((kt + 2) << 4); loadB((kt + 2) << 4);
        compute(1);
        storeA(0); storeB(0);
        __syncthreads();
    }
    loadA((NT - 1) << 4); loadB((NT - 1) << 4);
    compute(0);
    storeA(1); storeB(1);
    __syncthreads();
    compute(1);

    {
        int row = wm * 16 + g;
#pragma unroll
        for (int j = 0; j < 8; j++) {
            int col = n0 + wn * 64 + j * 8 + 2 * t;
            *(float2*)&C[(long)row * NN + col]       = make_float2(acc[j][0], acc[j][1]);
            *(float2*)&C[(long)(row + 8) * NN + col] = make_float2(acc[j][2], acc[j][3]);
        }
    }
}

// ============ gemmHH: merged Hs & Hc (K=512, N=512, ADD+tanh) ============
// grid z in [0,256):
//   z<128 : Hs[bz] = tanh(Sc + Cc @ L)     (nn; B = L [k,n])
//   z>=128: Hc[bz] = tanh(Cc + Sc @ L^T)   (nt; B = L [n,k])
__global__ __launch_bounds__(320, 2) void gemmHH(
    const float* __restrict__ Cc_, const float* __restrict__ Sc_,
    const float* __restrict__ L_,
    float* __restrict__ Hs_, float* __restrict__ Hc_)
{
    extern __shared__ unsigned char smem_raw[];
    float2* AsH = (float2*)smem_raw;
    float2* AsL = AsH + 1344;
    float2* BsH = AsH + 2688;
    float2* BsL = AsH + 4800;

    const int z = blockIdx.z;
    const int bz = z & 127;
    const bool nt = z >= 128;
    const float* A   = nt ? Sc_ + (long)bz * KK * NN : Cc_ + (long)bz * KK * TT;
    const float* B   = L_ + (long)bz * TT * NN;
    const float* Cad = nt ? Cc_ + (long)bz * KK * TT : Sc_ + (long)bz * KK * NN;
    float*       C   = nt ? Hc_ + (long)bz * KK * TT : Hs_ + (long)bz * KK * NN;
    constexpr int KD = 512;
    constexpr int N  = 512;

    const int n0 = blockIdx.x * 128;
    const int tid = threadIdx.x, lane = tid & 31, w = tid >> 5;
    const int g = lane >> 2, t = lane & 3;
    const int wm = w >> 1, wn = w & 1;

    auto aidx = [](int buf, int k8, int p, int r) {
        return (((buf * 2 + k8) * 4 + p) * 84 + r);
    };
    auto bidx = [](int buf, int k8, int p, int r) {
        return (((buf * 2 + k8) * 4 + p) * 132 + r);
    };

    float acc[8][4];
#pragma unroll
    for (int j = 0; j < 8; j++)
#pragma unroll
        for (int c = 0; c < 4; c++) acc[j][c] = 0.f;

    float4 va0, va1, vb0, vb1, vn0, vn1;
    const int lra = tid >> 1, lk8a = tid & 1;

    auto loadA = [&](int k0) {
        if (tid < 160) {
            const float* p = &A[(long)lra * KD + k0 + lk8a * 8];
            va0 = *(const float4*)p;
            va1 = *(const float4*)(p + 4);
        }
    };
    auto storeA = [&](int buf) {
        if (tid < 160) {
            float xs[4] = {va0.x, va0.y, va0.z, va0.w};
            float ys[4] = {va1.x, va1.y, va1.z, va1.w};
#pragma unroll
            for (int p = 0; p < 4; p++) {
                float hx = ftf32(xs[p]), hy = ftf32(ys[p]);
                AsH[aidx(buf, lk8a, p, lra)] = make_float2(hx, hy);
                AsL[aidx(buf, lk8a, p, lra)] = make_float2(ftf32(xs[p] - hx), ftf32(ys[p] - hy));
            }
        }
    };
    auto loadB = [&](int k0) {
        if (nt) {
            if (tid < 256) {
                const float* p = &B[(long)(n0 + lra) * KD + k0 + lk8a * 8];
                vb0 = *(const float4*)p;
                vb1 = *(const float4*)(p + 4);
            }
        } else {
            int s0 = tid, s1 = tid + 320;
            int k_a = s0 >> 5, nq_a = (s0 & 31) * 4;
            vn0 = *(const float4*)&B[(long)(k0 + k_a) * N + n0 + nq_a];
            if (s1 < 512) {
                int k_b = s1 >> 5, nq_b = (s1 & 31) * 4;
                vn1 = *(const float4*)&B[(long)(k0 + k_b) * N + n0 + nq_b];
            }
        }
    };
    auto storeB = [&](int buf) {
        if (nt) {
            if (tid < 256) {
                float xs[4] = {vb0.x, vb0.y, vb0.z, vb0.w};
                float ys[4] = {vb1.x, vb1.y, vb1.z, vb1.w};
#pragma unroll
                for (int p = 0; p < 4; p++) {
                    float hx = ftf32(xs[p]), hy = ftf32(ys[p]);
                    BsH[bidx(buf, lk8a, p, lra)] = make_float2(hx, hy);
                    BsL[bidx(buf, lk8a, p, lra)] = make_float2(ftf32(xs[p] - hx), ftf32(ys[p] - hy));
                }
            }
        } else {
#pragma unroll
            for (int h = 0; h < 2; h++) {
                int s = tid + h * 320;
                if (s < 512) {
                    int k = s >> 5, nq = (s & 31) * 4;
                    int k8 = k >> 3, p = k & 3, hi = (k >> 2) & 1;
                    float4 v = h ? vn1 : vn0;
                    float vv[4] = {v.x, v.y, v.z, v.w};
                    float* baseH = &BsH[bidx(buf, k8, p, nq)].x;
                    float* baseL = &BsL[bidx(buf, k8, p, nq)].x;
#pragma unroll
                    for (int c = 0; c < 4; c++) {
                        float hh = ftf32(vv[c]);
                        baseH[c * 2 + hi] = hh;
                        baseL[c * 2 + hi] = ftf32(vv[c] - hh);
                    }
                }
            }
        }
    };

    auto compute = [&](int buf) {
#pragma unroll
        for (int k8 = 0; k8 < 2; k8++) {
            int m = wm * 16 + g;
            float2 aH0 = AsH[aidx(buf, k8, t, m)];
            float2 aH8 = AsH[aidx(buf, k8, t, m + 8)];
            float2 aL0 = AsL[aidx(buf, k8, t, m)];
            float2 aL8 = AsL[aidx(buf, k8, t, m + 8)];
#pragma unroll
            for (int j = 0; j < 8; j++) {
                int n = wn * 64 + j * 8 + g;
                float2 bH = BsH[bidx(buf, k8, t, n)];
                float2 bL = BsL[bidx(buf, k8, t, n)];
                mma3(acc[j], aH0, aH8, aL0, aL8, bH, bL);
            }
        }
    };

    constexpr int NT = KD >> 4;   // 32
    loadA(0); loadB(0);
    storeA(0); storeB(0);
    __syncthreads();
#pragma unroll 1
    for (int kt = 0; kt < NT - 2; kt += 2) {
        loadA((kt + 1) << 4); loadB((kt + 1) << 4);
        compute(0);
        storeA(1); storeB(1);
        __syncthreads();
        loadA((kt + 2) << 4); loadB((kt + 2) << 4);
        compute(1);
        storeA(0); storeB(0);
        __syncthreads();
    }
    loadA((NT - 1) << 4); loadB((NT - 1) << 4);
    compute(0);
    storeA(1); storeB(1);
    __syncthreads();
    compute(1);

    {
        int row = wm * 16 + g;
#pragma unroll
        for (int j = 0; j < 8; j++) {
            int col = n0 + wn * 64 + j * 8 + 2 * t;
            float v0 = acc[j][0] + Cad[(long)row * N + col];
            float v1 = acc[j][1] + Cad[(long)row * N + col + 1];
            float v2 = acc[j][2] + Cad[(long)(row + 8) * N + col];
            float v3 = acc[j][3] + Cad[(long)(row + 8) * N + col + 1];
            v0 = tanhf(v0); v1 = tanhf(v1); v2 = tanhf(v2); v3 = tanhf(v3);
            *(float2*)&C[(long)row * N + col]       = make_float2(v0, v1);
            *(float2*)&C[(long)(row + 8) * N + col] = make_float2(v2, v3);
        }
    }
}

// --------------- attention: logits -> softmax -> pooling ---------------
__global__ __launch_bounds__(256) void attn_k(
    const float* __restrict__ Hs, const float* __restrict__ whs,
    const float* __restrict__ Xs,
    const float* __restrict__ Hc, const float* __restrict__ whc,
    const float* __restrict__ Xc,
    float* __restrict__ out)
{
    const int b = blockIdx.x;
    const int side = blockIdx.y;
    const float* H  = side ? Hc  : Hs;
    const float* wh = side ? whc : whs;
    const float* X  = side ? Xc  : Xs;
    const int outOff = side ? DD : 0;

    const int tid = threadIdx.x;
    __shared__ float wgt[512];
    __shared__ float red[256];
    __shared__ float whsm[KK];

    if (tid < KK) whsm[tid] = wh[tid];
    __syncthreads();

    for (int n = tid; n < 512; n += 256) {
        const float* hp = H + (long)b * KK * 512 + n;
        float acc = 0.f;
#pragma unroll 8
        for (int k = 0; k < KK; k++) acc = fmaf(whsm[k], hp[(long)k * 512], acc);
        wgt[n] = acc;
    }
    __syncthreads();

    float m = fmaxf(wgt[tid], wgt[tid + 256]);
    red[tid] = m;
    __syncthreads();
    for (int s = 128; s > 0; s >>= 1) {
        if (tid < s) red[tid] = fmaxf(red[tid], red[tid + s]);
        __syncthreads();
    }
    const float mx = red[0];
    __syncthreads();

    float e0 = expf(wgt[tid] - mx);
    float e1 = expf(wgt[tid + 256] - mx);
    wgt[tid] = e0;
    wgt[tid + 256] = e1;
    red[tid] = e0 + e1;
    __syncthreads();
    for (int s = 128; s > 0; s >>= 1) {
        if (tid < s) red[tid] += red[tid + s];
        __syncthreads();
    }
    const float inv = 1.f / red[0];
    __syncthreads();

    const float* xp = X + (long)b * 512 * DD + tid;
    float acc = 0.f;
    for (int n = 0; n < 512; n++) acc = fmaf(xp[(long)n * DD], wgt[n], acc);
    out[(long)b * 512 + outOff + tid] = acc * inv;
}

// ------------------------------- launch -------------------------------
extern "C" void kernel_launch(void* const* d_in, const int* in_sizes, int n_in,
                              void* d_out, int out_size)
{
    const float* content  = (const float*)d_in[0];
    const float* comments = (const float*)d_in[1];
    const float* Wl       = (const float*)d_in[2];
    const float* Wc       = (const float*)d_in[3];
    const float* Ws       = (const float*)d_in[4];
    const float* whs      = (const float*)d_in[5];
    const float* whc      = (const float*)d_in[6];
    float* out = (float*)d_out;

    float *CT, *L, *Sc, *Cc, *Hs, *Hc, *WlT;
    cudaGetSymbolAddress((void**)&CT,  g_CT);
    cudaGetSymbolAddress((void**)&L,   g_L);
    cudaGetSymbolAddress((void**)&Sc,  g_Sc);
    cudaGetSymbolAddress((void**)&Cc,  g_Cc);
    cudaGetSymbolAddress((void**)&Hs,  g_Hs);
    cudaGetSymbolAddress((void**)&Hc,  g_Hc);
    cudaGetSymbolAddress((void**)&WlT, g_WlT);

    cudaFuncSetAttribute(gemmA<DD, true,  false, false>, cudaFuncAttributeMaxDynamicSharedMemorySize, SMEM_A_BYTES);
    cudaFuncSetAttribute(gemmA<DD, true,  false, true >, cudaFuncAttributeMaxDynamicSharedMemorySize, SMEM_A_BYTES);
    cudaFuncSetAttribute(gemmSC, cudaFuncAttributeMaxDynamicSharedMemorySize, SMEM_B_BYTES);
    cudaFuncSetAttribute(gemmHH, cudaFuncAttributeMaxDynamicSharedMemorySize, SMEM_B_BYTES);

    // WlT = Wl^T (tiny)
    transW<<<dim3(8, 8), 256>>>(Wl, WlT);

    // CT[b] = comments[b] @ Wl = comments[b] @ WlT^T   [512,256], K=256 (nt)
    gemmA<DD, true, false, false><<<dim3(2, 4, BB), 256, SMEM_A_BYTES>>>(
        comments, WlT, nullptr, CT, DD, (long)TT * DD, 0, (long)TT * DD);

    // Sc & Cc merged: [80,512], K=256 (nt)
    gemmSC<<<dim3(4, 1, 2 * BB), 320, SMEM_B_BYTES>>>(
        Ws, content, Sc, Wc, comments, Cc);

    // L[b] = tanh(CT[b] @ content[b]^T)  [512,512], K=256 (nt)
    gemmA<DD, true, false, true><<<dim3(4, 4, BB), 256, SMEM_A_BYTES>>>(
        CT, content, nullptr, L, NN, (long)TT * DD, (long)NN * DD, (long)TT * NN);

    // Hs & Hc merged: [80,512], K=512
    gemmHH<<<dim3(4, 1, 2 * BB), 320, SMEM_B_BYTES>>>(Cc, Sc, L, Hs, Hc);

    attn_k<<<dim3(BB, 2), 256>>>(Hs, whs, content, Hc, whc, comments, out);
}